// round 7
// baseline (speedup 1.0000x reference)
#include <cuda_runtime.h>
#include <math.h>
#include <stdint.h>

#define Nn 50000
#define Ee 800000
#define Gg 512
#define EPS 1e-5f
#define NCH 98            // ceil(50000/512) chunks for scan
#define B_STATS 1000
#define B_DEG   1563      // ceil(800000/512)
#define B_BP    98        // ceil(50000/512)
#define B_NODET 6250      // node_t blocks (8 nodes each)
#define B_SCAT  3125      // scatter blocks (256 edges each)

// ------------------------- device scratch (static, no allocs) ---------------
__device__ float g_sum1[512], g_sumsq1[512];
__device__ __align__(16) float g_Wc2[16 * 512];
__device__ float g_bc2[16];
__device__ __align__(16) float g_z[(size_t)Nn * 48];
__device__ float g_sum2[48], g_sumsq2[48];
__device__ __align__(16) float g_t[(size_t)Nn * 64];   // interleaved: (k, k+32) float2 pairs
__device__ float g_wsrc[4 * 64], g_wdst[4 * 64];
__device__ __align__(16) float g_asrc[Nn * 4];
__device__ __align__(16) float g_adst[Nn * 4];
__device__ int g_deg[Nn];
__device__ int g_rowptr[Nn + 1];
__device__ int g_cursor[Nn];
__device__ int g_chunksum[NCH];
__device__ int g_col[Ee];
__device__ int g_gptr[Gg + 1];
__device__ __align__(16) float g_aggt[(size_t)Nn * 256];
__device__ __align__(16) float g_out[(size_t)Nn * 256];
__device__ float g_sum3[256], g_sumsq3[256];

// ------------------------- helpers ------------------------------------------
__device__ __forceinline__ float warp_sum(float v) {
    #pragma unroll
    for (int off = 16; off; off >>= 1) v += __shfl_xor_sync(0xffffffffu, v, off);
    return v;
}
__device__ __forceinline__ int warp_sum_i(int v) {
    #pragma unroll
    for (int off = 16; off; off >>= 1) v += __shfl_xor_sync(0xffffffffu, v, off);
    return v;
}

// ------- init (per-launch reset) + att-vector fold (no dependencies) --------
__global__ void k_init(const float* __restrict__ Wg,
                       const float* __restrict__ att_src, const float* __restrict__ att_dst) {
    int b = blockIdx.x, t = threadIdx.x;
    if (b < 196) {
        int i = b * 256 + t;
        int stride = 196 * 256;
        for (int j = i; j < Nn; j += stride) g_deg[j] = 0;
        if (i < 512) { g_sum1[i] = 0.f; g_sumsq1[i] = 0.f; }
        if (i < 256) { g_sum3[i] = 0.f; g_sumsq3[i] = 0.f; }
        if (i < 48)  { g_sum2[i] = 0.f; g_sumsq2[i] = 0.f; }
    } else {
        int hd = b - 196;
        __shared__ float as[64], ad[64];
        if (t < 64) { as[t] = att_src[hd * 64 + t]; ad[t] = att_dst[hd * 64 + t]; }
        __syncthreads();
        if (t < 64) {
            float s = 0.f, d = 0.f;
            #pragma unroll 8
            for (int j = 0; j < 64; j++) {
                float w = Wg[(size_t)(hd * 64 + j) * 64 + t];
                s += as[j] * w;
                d += ad[j] * w;
            }
            g_wsrc[hd * 64 + t] = s;
            g_wdst[hd * 64 + t] = d;
        }
    }
}

// ---- merged: bn1 stats | degree count | batch group boundaries --------------
__global__ void k_pre(const float* __restrict__ x, const int* __restrict__ ei,
                      const int* __restrict__ batch) {
    int b = blockIdx.x;
    if (b < B_STATS) {
        int c = threadIdx.x;  // 512 threads
        float s = 0.f, q = 0.f;
        for (int r = b; r < Nn; r += B_STATS) {
            float v = x[(size_t)r * 544 + c];
            s += v; q += v * v;
        }
        atomicAdd(&g_sum1[c], s);
        atomicAdd(&g_sumsq1[c], q);
    } else if (b < B_STATS + B_DEG) {
        int e = (b - B_STATS) * 512 + threadIdx.x;
        if (e < Ee) atomicAdd(&g_deg[ei[Ee + e]], 1);
    } else {
        int n = (b - B_STATS - B_DEG) * 512 + threadIdx.x;
        if (n < Nn) {
            int bb = batch[n];
            int prev = (n == 0) ? -1 : batch[n - 1];
            for (int g = prev + 1; g <= bb; g++) g_gptr[g] = n;
            if (n == Nn - 1) for (int g = bb + 1; g <= Gg; g++) g_gptr[g] = Nn;
        }
    }
}

// ---- merged: fold bn1 into Wc (blocks 0..15) | scan phase 1 (blocks 16..113)
__global__ void k_fold_scan1(const float* __restrict__ Wc, const float* __restrict__ bc,
                             const float* __restrict__ bn1_g, const float* __restrict__ bn1_b) {
    int b = blockIdx.x, t = threadIdx.x;  // 512 threads
    if (b < 16) {
        __shared__ float red[512];
        const float invN = 1.f / Nn;
        float mean = g_sum1[t] * invN;
        float var  = g_sumsq1[t] * invN - mean * mean;
        float r = rsqrtf(var + EPS);
        float sc = r * bn1_g[t];
        float sh = bn1_b[t] - mean * sc;
        float w = Wc[b * 512 + t];
        g_Wc2[b * 512 + t] = w * sc;
        red[t] = w * sh;
        __syncthreads();
        for (int s = 256; s; s >>= 1) { if (t < s) red[t] += red[t + s]; __syncthreads(); }
        if (t == 0) g_bc2[b] = bc[b] + red[0];
    } else {
        int chunk = b - 16;
        int idx = chunk * 512 + t;
        int d = (idx < Nn) ? g_deg[idx] : 0;
        int s = warp_sum_i(d);
        __shared__ int sh[16];
        if ((t & 31) == 0) sh[t >> 5] = s;
        __syncthreads();
        if (t < 16) {
            int v = sh[t];
            #pragma unroll
            for (int off = 8; off; off >>= 1) v += __shfl_xor_sync(0xffffu, v, off);
            if (t == 0) g_chunksum[chunk] = v;
        }
    }
}

// ---- merged: scan phase 2+3 (blocks 0..97) | node_z (blocks 98..3222) ------
__global__ void k_scan3_nodez(const float* __restrict__ x,
                              const float* __restrict__ ln_g, const float* __restrict__ ln_b) {
    int b = blockIdx.x, tid = threadIdx.x;  // 512 threads
    if (b < NCH) {
        __shared__ int sh[512];
        __shared__ int ssum[16];
        __shared__ int off_s;
        // inline scan2: exclusive offset for this chunk = sum of earlier chunk sums
        int v = (tid < b) ? g_chunksum[tid] : 0;
        v = warp_sum_i(v);
        if ((tid & 31) == 0) ssum[tid >> 5] = v;
        __syncthreads();
        if (tid == 0) {
            int o = 0;
            #pragma unroll
            for (int i = 0; i < 16; i++) o += ssum[i];
            off_s = o;
        }
        int idx = b * 512 + tid;
        int d = (idx < Nn) ? g_deg[idx] : 0;
        sh[tid] = d;
        __syncthreads();
        for (int off = 1; off < 512; off <<= 1) {
            int u = (tid >= off) ? sh[tid - off] : 0;
            __syncthreads();
            sh[tid] += u;
            __syncthreads();
        }
        if (idx < Nn) {
            int pos = off_s + sh[tid] - d;
            g_rowptr[idx] = pos;
            g_cursor[idx] = pos;
        }
        if (idx == Nn - 1) g_rowptr[Nn] = Ee;
    } else {
        __shared__ float sh_s[48], sh_q[48];
        if (tid < 48) { sh_s[tid] = 0.f; sh_q[tid] = 0.f; }
        __syncthreads();
        int w = tid >> 5, lane = tid & 31;
        int n = (b - NCH) * 16 + w;   // 3125 blocks x 16 warps = 50000
        const float* row = x + (size_t)n * 544;

        float fv = row[512 + lane];
        float mu = warp_sum(fv) * (1.f / 32.f);
        float qq = warp_sum(fv * fv) * (1.f / 32.f);
        float fr = rsqrtf(qq - mu * mu + EPS);
        float fn = (fv - mu) * fr * ln_g[lane] + ln_b[lane];

        float4 xv[4];
        #pragma unroll
        for (int i = 0; i < 4; i++)
            xv[i] = *(const float4*)&row[4 * lane + 128 * i];

        float xc = 0.f;
        #pragma unroll
        for (int o = 0; o < 16; o++) {
            float a = 0.f;
            #pragma unroll
            for (int i = 0; i < 4; i++) {
                float4 wv = *(const float4*)&g_Wc2[o * 512 + 4 * lane + 128 * i];
                a += xv[i].x * wv.x + xv[i].y * wv.y + xv[i].z * wv.z + xv[i].w * wv.w;
            }
            float v = warp_sum(a);
            if (lane == o) xc = v + g_bc2[o];
        }

        float* zr = g_z + (size_t)n * 48;
        if (lane < 16) zr[lane] = xc;
        zr[16 + lane] = fn;

        if (lane < 16) { atomicAdd(&sh_s[lane], xc); atomicAdd(&sh_q[lane], xc * xc); }
        atomicAdd(&sh_s[16 + lane], fn);
        atomicAdd(&sh_q[16 + lane], fn * fn);
        __syncthreads();
        if (tid < 48) { atomicAdd(&g_sum2[tid], sh_s[tid]); atomicAdd(&g_sumsq2[tid], sh_q[tid]); }
    }
}

// ---- merged: node_t with inline Wp/bn2 fold (blocks 0..6249) | scatter ------
__global__ void k_nodet_scatter(const float* __restrict__ Wp, const float* __restrict__ bp,
                                const float* __restrict__ bn2_g, const float* __restrict__ bn2_b,
                                const int* __restrict__ ei) {
    int b = blockIdx.x, tid = threadIdx.x;  // 256 threads
    if (b < B_NODET) {
        __shared__ float sc2[48], sh2[48];
        __shared__ float wp[64 * 49];
        __shared__ float bp2s[64];
        __shared__ float zb[8][48];
        if (tid < 48) {
            const float invN = 1.f / Nn;
            float mean = g_sum2[tid] * invN;
            float var  = g_sumsq2[tid] * invN - mean * mean;
            float r = rsqrtf(var + EPS);
            float sc = r * bn2_g[tid];
            sc2[tid] = sc;
            sh2[tid] = bn2_b[tid] - mean * sc;
        }
        __syncthreads();
        for (int i = tid; i < 64 * 48; i += 256) {
            int o = i / 48, k = i - o * 48;
            wp[o * 49 + k] = Wp[i] * sc2[k];
        }
        if (tid < 64) {
            float a = bp[tid];
            #pragma unroll 8
            for (int k = 0; k < 48; k++) a += Wp[tid * 48 + k] * sh2[k];
            bp2s[tid] = a;
        }
        __syncthreads();

        int w = tid >> 5, lane = tid & 31;
        int n = b * 8 + w;
        const float* zr = g_z + (size_t)n * 48;
        zb[w][lane] = zr[lane];
        if (lane < 16) zb[w][32 + lane] = zr[32 + lane];
        __syncwarp();
        float t0 = bp2s[lane], t1 = bp2s[lane + 32];
        #pragma unroll
        for (int k = 0; k < 48; k++) {
            float zv = zb[w][k];
            t0 += wp[lane * 49 + k] * zv;
            t1 += wp[(lane + 32) * 49 + k] * zv;
        }
        t0 = fmaxf(t0, 0.f);
        t1 = fmaxf(t1, 0.f);
        ((float2*)g_t)[(size_t)n * 32 + lane] = make_float2(t0, t1);

        #pragma unroll
        for (int hd = 0; hd < 4; hd++) {
            float ps = t0 * g_wsrc[hd * 64 + lane] + t1 * g_wsrc[hd * 64 + 32 + lane];
            float pd = t0 * g_wdst[hd * 64 + lane] + t1 * g_wdst[hd * 64 + 32 + lane];
            float vs = warp_sum(ps);
            float vd = warp_sum(pd);
            if (lane == 0) { g_asrc[n * 4 + hd] = vs; g_adst[n * 4 + hd] = vd; }
        }
    } else {
        int e = (b - B_NODET) * 256 + tid;
        int di = ei[Ee + e];
        int pos = atomicAdd(&g_cursor[di], 1);
        g_col[pos] = ei[e];
    }
}

// --------- fused softmax + aggregation in t-space: warp per dst node --------
__global__ void k_agg() {
    int tid = threadIdx.x;
    int w = tid >> 5, lane = tid & 31;
    int n = blockIdx.x * 8 + w;
    int r0 = g_rowptr[n], r1 = g_rowptr[n + 1];
    float4 ad = *(const float4*)&g_adst[n * 4];
    const float2* t2 = (const float2*)g_t;

    float acc[8];
    #pragma unroll
    for (int i = 0; i < 8; i++) acc[i] = 0.f;
    float s0 = 0.f, s1 = 0.f, s2 = 0.f, s3 = 0.f;

    for (int base = r0; base < r1; base += 32) {
        int cnt = min(32, r1 - base);
        int si = 0;
        float ex0 = 0.f, ex1 = 0.f, ex2 = 0.f, ex3 = 0.f;
        if (lane < cnt) {
            si = g_col[base + lane];
            float4 as = *(const float4*)&g_asrc[si * 4];
            float e0 = as.x + ad.x, e1 = as.y + ad.y, e2 = as.z + ad.z, e3 = as.w + ad.w;
            e0 = e0 > 0.f ? e0 : 0.2f * e0;
            e1 = e1 > 0.f ? e1 : 0.2f * e1;
            e2 = e2 > 0.f ? e2 : 0.2f * e2;
            e3 = e3 > 0.f ? e3 : 0.2f * e3;
            ex0 = __expf(e0); ex1 = __expf(e1); ex2 = __expf(e2); ex3 = __expf(e3);
            s0 += ex0; s1 += ex1; s2 += ex2; s3 += ex3;
        }
        for (int j = 0; j < cnt; j++) {
            int sj   = __shfl_sync(0xffffffffu, si, j);
            float a0 = __shfl_sync(0xffffffffu, ex0, j);
            float a1 = __shfl_sync(0xffffffffu, ex1, j);
            float a2 = __shfl_sync(0xffffffffu, ex2, j);
            float a3 = __shfl_sync(0xffffffffu, ex3, j);
            float2 u = t2[(size_t)sj * 32 + lane];
            acc[0] += a0 * u.x; acc[1] += a0 * u.y;
            acc[2] += a1 * u.x; acc[3] += a1 * u.y;
            acc[4] += a2 * u.x; acc[5] += a2 * u.y;
            acc[6] += a3 * u.x; acc[7] += a3 * u.y;
        }
    }
    s0 = warp_sum(s0); s1 = warp_sum(s1); s2 = warp_sum(s2); s3 = warp_sum(s3);
    float i0 = 1.f / fmaxf(s0, 1e-16f);
    float i1 = 1.f / fmaxf(s1, 1e-16f);
    float i2 = 1.f / fmaxf(s2, 1e-16f);
    float i3 = 1.f / fmaxf(s3, 1e-16f);
    float* o = g_aggt + (size_t)n * 256;
    o[lane]            = acc[0] * i0;  o[lane + 32]       = acc[1] * i0;
    o[64 + lane]       = acc[2] * i1;  o[64 + 32 + lane]  = acc[3] * i1;
    o[128 + lane]      = acc[4] * i2;  o[128 + 32 + lane] = acc[5] * i2;
    o[192 + lane]      = acc[6] * i3;  o[192 + 32 + lane] = acc[7] * i3;
}

// -------- GEMM: out[:, hd] = aggt[:, hd] @ Wg[hd]^T + reduced bn3 stats ------
__global__ void k_gemm_out(const float* __restrict__ Wg) {
    __shared__ float tsh[64 * 68];
    __shared__ float wsh[64 * 68];
    int n0 = blockIdx.x * 64;
    int hd = blockIdx.y;
    int out0 = hd * 64;
    int tid = threadIdx.x;

    for (int i = tid; i < 64 * 16; i += 256) {
        int r = i >> 4, c = (i & 15) << 2;
        float4 v = make_float4(0.f, 0.f, 0.f, 0.f);
        int n = n0 + r;
        if (n < Nn) v = *(const float4*)&g_aggt[(size_t)n * 256 + out0 + c];
        *(float4*)&tsh[r * 68 + c] = v;
        float4 wv = *(const float4*)&Wg[(size_t)(out0 + r) * 64 + c];
        *(float4*)&wsh[r * 68 + c] = wv;
    }
    __syncthreads();

    int tx = tid & 31, ty = tid >> 5;
    float acc[8][2];
    #pragma unroll
    for (int i = 0; i < 8; i++) { acc[i][0] = 0.f; acc[i][1] = 0.f; }

    #pragma unroll 4
    for (int k = 0; k < 64; k += 4) {
        float4 tv[8], wv[2];
        #pragma unroll
        for (int i = 0; i < 8; i++) tv[i] = *(float4*)&tsh[(ty * 8 + i) * 68 + k];
        wv[0] = *(float4*)&wsh[tx * 68 + k];
        wv[1] = *(float4*)&wsh[(tx + 32) * 68 + k];
        #pragma unroll
        for (int i = 0; i < 8; i++) {
            #pragma unroll
            for (int o = 0; o < 2; o++) {
                acc[i][o] += tv[i].x * wv[o].x;
                acc[i][o] += tv[i].y * wv[o].y;
                acc[i][o] += tv[i].z * wv[o].z;
                acc[i][o] += tv[i].w * wv[o].w;
            }
        }
    }
    float ps0 = 0.f, pq0 = 0.f, ps1 = 0.f, pq1 = 0.f;
    #pragma unroll
    for (int i = 0; i < 8; i++) {
        int n = n0 + ty * 8 + i;
        if (n < Nn) {
            g_out[(size_t)n * 256 + out0 + tx]      = acc[i][0];
            g_out[(size_t)n * 256 + out0 + tx + 32] = acc[i][1];
            ps0 += acc[i][0]; pq0 += acc[i][0] * acc[i][0];
            ps1 += acc[i][1]; pq1 += acc[i][1] * acc[i][1];
        }
    }
    __syncthreads();
    tsh[ty * 32 + tx]       = ps0;
    tsh[256 + ty * 32 + tx] = pq0;
    tsh[512 + ty * 32 + tx] = ps1;
    tsh[768 + ty * 32 + tx] = pq1;
    __syncthreads();
    if (ty == 0) {
        float a0 = 0.f, a1 = 0.f, a2 = 0.f, a3 = 0.f;
        #pragma unroll
        for (int j = 0; j < 8; j++) {
            a0 += tsh[j * 32 + tx];
            a1 += tsh[256 + j * 32 + tx];
            a2 += tsh[512 + j * 32 + tx];
            a3 += tsh[768 + j * 32 + tx];
        }
        atomicAdd(&g_sum3[out0 + tx], a0);
        atomicAdd(&g_sumsq3[out0 + tx], a1);
        atomicAdd(&g_sum3[out0 + tx + 32], a2);
        atomicAdd(&g_sumsq3[out0 + tx + 32], a3);
    }
}

// -------- per-group: bn3 + elu + mean-pool (contiguous, no atomics) + head --
__global__ void k_pool_head(const float* __restrict__ bn3_g, const float* __restrict__ bn3_b,
                            const float* __restrict__ W1, const float* __restrict__ b1,
                            const float* __restrict__ W2, const float* __restrict__ b2,
                            float* __restrict__ out) {
    __shared__ float p[256];
    __shared__ float hm[64];
    int g = blockIdx.x, c = threadIdx.x;
    const float invN = 1.f / Nn;
    float mean = g_sum3[c] * invN;
    float var  = g_sumsq3[c] * invN - mean * mean;
    float r = rsqrtf(var + EPS);
    float sc = r * bn3_g[c];
    float sh = bn3_b[c] - mean * sc;
    int r0 = g_gptr[g], r1 = g_gptr[g + 1];
    float s = 0.f;
    for (int n = r0; n < r1; n++) {
        float v = g_out[(size_t)n * 256 + c] * sc + sh;
        v = v > 0.f ? v : (__expf(v) - 1.f);
        s += v;
    }
    p[c] = s / fmaxf((float)(r1 - r0), 1.f);
    __syncthreads();
    if (c < 64) {
        float a = b1[c];
        #pragma unroll 8
        for (int k = 0; k < 256; k++) a += p[k] * W1[c * 256 + k];
        hm[c] = fmaxf(a, 0.f);
    }
    __syncthreads();
    if (c < 2) {
        float a = b2[c];
        #pragma unroll
        for (int k = 0; k < 64; k++) a += hm[k] * W2[c * 64 + k];
        out[g * 2 + c] = a;
    }
}

// ------------------------- launch ---------------------------------------------
extern "C" void kernel_launch(void* const* d_in, const int* in_sizes, int n_in,
                              void* d_out, int out_size) {
    const float* x       = (const float*)d_in[0];
    const int*   ei      = (const int*)d_in[1];
    const int*   batch   = (const int*)d_in[2];
    const float* ln_g    = (const float*)d_in[3];
    const float* ln_b    = (const float*)d_in[4];
    const float* bn1_g   = (const float*)d_in[5];
    const float* bn1_b   = (const float*)d_in[6];
    const float* Wc      = (const float*)d_in[7];
    const float* bc      = (const float*)d_in[8];
    const float* bn2_g   = (const float*)d_in[9];
    const float* bn2_b   = (const float*)d_in[10];
    const float* Wp      = (const float*)d_in[11];
    const float* bp      = (const float*)d_in[12];
    const float* Wg      = (const float*)d_in[13];
    const float* att_src = (const float*)d_in[14];
    const float* att_dst = (const float*)d_in[15];
    // d_in[16] = bg : cancels under bn3 (pure mean shift) -> unused
    const float* bn3_g   = (const float*)d_in[17];
    const float* bn3_b   = (const float*)d_in[18];
    const float* W1      = (const float*)d_in[19];
    const float* b1      = (const float*)d_in[20];
    const float* W2      = (const float*)d_in[21];
    const float* b2      = (const float*)d_in[22];
    float* out = (float*)d_out;

    k_init<<<200, 256>>>(Wg, att_src, att_dst);
    k_pre<<<B_STATS + B_DEG + B_BP, 512>>>(x, ei, batch);
    k_fold_scan1<<<16 + NCH, 512>>>(Wc, bc, bn1_g, bn1_b);
    k_scan3_nodez<<<NCH + 3125, 512>>>(x, ln_g, ln_b);
    k_nodet_scatter<<<B_NODET + B_SCAT, 256>>>(Wp, bp, bn2_g, bn2_b, ei);
    k_agg<<<6250, 256>>>();
    dim3 gh(782, 4);
    k_gemm_out<<<gh, 256>>>(Wg);
    k_pool_head<<<Gg, 256>>>(bn3_g, bn3_b, W1, b1, W2, b2, out);
}

// round 8
// speedup vs baseline: 1.1686x; 1.1686x over previous
#include <cuda_runtime.h>
#include <math.h>
#include <stdint.h>

#define Nn 50000
#define Ee 800000
#define Gg 512
#define EPS 1e-5f
#define NCH 98            // ceil(50000/512) chunks for scan
#define B_STATS 1000
#define B_DEG   1563      // ceil(800000/512)
#define B_BP    98        // ceil(50000/512)
#define B_NZ    1563      // nodez blocks (32 nodes each)

// ------------------------- device scratch (static, no allocs) ---------------
__device__ float g_sum1[512], g_sumsq1[512];
__device__ __align__(16) float g_Wc2[16 * 512];
__device__ float g_bc2[16];
__device__ __align__(16) float g_z[(size_t)Nn * 48];
__device__ float g_sum2[48], g_sumsq2[48];
__device__ float g_Wp2[64 * 48], g_bp2[64];
__device__ __align__(16) float g_t[(size_t)Nn * 64];   // interleaved (k, k+32) float2
__device__ float g_wsrc[4 * 64], g_wdst[4 * 64];
__device__ __align__(16) float g_asrc[Nn * 4];
__device__ __align__(16) float g_adst[Nn * 4];
__device__ int g_deg[Nn];
__device__ int g_rowptr[Nn + 1];
__device__ int g_cursor[Nn];
__device__ int g_chunksum[NCH];
__device__ int g_col[Ee];
__device__ int g_gptr[Gg + 1];
__device__ __align__(16) float g_aggt[(size_t)Nn * 256];
__device__ __align__(16) float g_out[(size_t)Nn * 256];
__device__ float g_sum3[256], g_sumsq3[256];

// ------------------------- helpers ------------------------------------------
__device__ __forceinline__ float warp_sum(float v) {
    #pragma unroll
    for (int off = 16; off; off >>= 1) v += __shfl_xor_sync(0xffffffffu, v, off);
    return v;
}
__device__ __forceinline__ int warp_sum_i(int v) {
    #pragma unroll
    for (int off = 16; off; off >>= 1) v += __shfl_xor_sync(0xffffffffu, v, off);
    return v;
}

// ------- init (per-launch reset) + att-vector fold (no dependencies) --------
__global__ void k_init(const float* __restrict__ Wg,
                       const float* __restrict__ att_src, const float* __restrict__ att_dst) {
    int b = blockIdx.x, t = threadIdx.x;
    if (b < 196) {
        int i = b * 256 + t;
        int stride = 196 * 256;
        for (int j = i; j < Nn; j += stride) g_deg[j] = 0;
        if (i < 512) { g_sum1[i] = 0.f; g_sumsq1[i] = 0.f; }
        if (i < 256) { g_sum3[i] = 0.f; g_sumsq3[i] = 0.f; }
        if (i < 48)  { g_sum2[i] = 0.f; g_sumsq2[i] = 0.f; }
    } else {
        int hd = b - 196;
        __shared__ float as[64], ad[64];
        if (t < 64) { as[t] = att_src[hd * 64 + t]; ad[t] = att_dst[hd * 64 + t]; }
        __syncthreads();
        if (t < 64) {
            float s = 0.f, d = 0.f;
            #pragma unroll 8
            for (int j = 0; j < 64; j++) {
                float w = Wg[(size_t)(hd * 64 + j) * 64 + t];
                s += as[j] * w;
                d += ad[j] * w;
            }
            g_wsrc[hd * 64 + t] = s;
            g_wdst[hd * 64 + t] = d;
        }
    }
}

// ---- merged: bn1 stats | degree count | batch group boundaries --------------
__global__ void k_pre(const float* __restrict__ x, const int* __restrict__ ei,
                      const int* __restrict__ batch) {
    int b = blockIdx.x;
    if (b < B_STATS) {
        int c = threadIdx.x;  // 512 threads
        float s = 0.f, q = 0.f;
        for (int r = b; r < Nn; r += B_STATS) {
            float v = x[(size_t)r * 544 + c];
            s += v; q += v * v;
        }
        atomicAdd(&g_sum1[c], s);
        atomicAdd(&g_sumsq1[c], q);
    } else if (b < B_STATS + B_DEG) {
        int e = (b - B_STATS) * 512 + threadIdx.x;
        if (e < Ee) atomicAdd(&g_deg[ei[Ee + e]], 1);
    } else {
        int n = (b - B_STATS - B_DEG) * 512 + threadIdx.x;
        if (n < Nn) {
            int bb = batch[n];
            int prev = (n == 0) ? -1 : batch[n - 1];
            for (int g = prev + 1; g <= bb; g++) g_gptr[g] = n;
            if (n == Nn - 1) for (int g = bb + 1; g <= Gg; g++) g_gptr[g] = Nn;
        }
    }
}

// ---- merged: fold bn1 into Wc (blocks 0..15) | scan phase 1 (blocks 16..113)
__global__ void k_fold_scan1(const float* __restrict__ Wc, const float* __restrict__ bc,
                             const float* __restrict__ bn1_g, const float* __restrict__ bn1_b) {
    int b = blockIdx.x, t = threadIdx.x;  // 512 threads
    if (b < 16) {
        __shared__ float red[512];
        const float invN = 1.f / Nn;
        float mean = g_sum1[t] * invN;
        float var  = g_sumsq1[t] * invN - mean * mean;
        float r = rsqrtf(var + EPS);
        float sc = r * bn1_g[t];
        float sh = bn1_b[t] - mean * sc;
        float w = Wc[b * 512 + t];
        g_Wc2[b * 512 + t] = w * sc;
        red[t] = w * sh;
        __syncthreads();
        for (int s = 256; s; s >>= 1) { if (t < s) red[t] += red[t + s]; __syncthreads(); }
        if (t == 0) g_bc2[b] = bc[b] + red[0];
    } else {
        int chunk = b - 16;
        int idx = chunk * 512 + t;
        int d = (idx < Nn) ? g_deg[idx] : 0;
        int s = warp_sum_i(d);
        __shared__ int sh[16];
        if ((t & 31) == 0) sh[t >> 5] = s;
        __syncthreads();
        if (t < 16) {
            int v = sh[t];
            #pragma unroll
            for (int off = 8; off; off >>= 1) v += __shfl_xor_sync(0xffffu, v, off);
            if (t == 0) g_chunksum[chunk] = v;
        }
    }
}

// ---- merged: scan phase 2+3 (blocks 0..97) | node_z 2-nodes/warp (98+) -----
__global__ void k_scan3_nodez(const float* __restrict__ x,
                              const float* __restrict__ ln_g, const float* __restrict__ ln_b) {
    int b = blockIdx.x, tid = threadIdx.x;  // 512 threads
    if (b < NCH) {
        __shared__ int sh[512];
        __shared__ int ssum[16];
        __shared__ int off_s;
        int v = (tid < b) ? g_chunksum[tid] : 0;
        v = warp_sum_i(v);
        if ((tid & 31) == 0) ssum[tid >> 5] = v;
        __syncthreads();
        if (tid == 0) {
            int o = 0;
            #pragma unroll
            for (int i = 0; i < 16; i++) o += ssum[i];
            off_s = o;
        }
        int idx = b * 512 + tid;
        int d = (idx < Nn) ? g_deg[idx] : 0;
        sh[tid] = d;
        __syncthreads();
        for (int off = 1; off < 512; off <<= 1) {
            int u = (tid >= off) ? sh[tid - off] : 0;
            __syncthreads();
            sh[tid] += u;
            __syncthreads();
        }
        if (idx < Nn) {
            int pos = off_s + sh[tid] - d;
            g_rowptr[idx] = pos;
            g_cursor[idx] = pos;
        }
        if (idx == Nn - 1) g_rowptr[Nn] = Ee;
    } else {
        __shared__ float sh_s[48], sh_q[48];
        if (tid < 48) { sh_s[tid] = 0.f; sh_q[tid] = 0.f; }
        __syncthreads();
        int w = tid >> 5, lane = tid & 31;
        int n0 = (b - NCH) * 32 + w * 2;   // 2 nodes per warp
        int n1 = n0 + 1;
        bool v0 = n0 < Nn, v1 = n1 < Nn;   // warp-uniform
        const float* row0 = x + (size_t)n0 * 544;
        const float* row1 = x + (size_t)n1 * 544;

        // layernorm on f for both nodes
        float fn0 = 0.f, fn1 = 0.f;
        if (v0) {
            float fv = row0[512 + lane];
            float mu = warp_sum(fv) * (1.f / 32.f);
            float qq = warp_sum(fv * fv) * (1.f / 32.f);
            fn0 = (fv - mu) * rsqrtf(qq - mu * mu + EPS) * ln_g[lane] + ln_b[lane];
        }
        if (v1) {
            float fv = row1[512 + lane];
            float mu = warp_sum(fv) * (1.f / 32.f);
            float qq = warp_sum(fv * fv) * (1.f / 32.f);
            fn1 = (fv - mu) * rsqrtf(qq - mu * mu + EPS) * ln_g[lane] + ln_b[lane];
        }

        // load x rows (vectorized)
        float4 xv0[4], xv1[4];
        #pragma unroll
        for (int i = 0; i < 4; i++) {
            xv0[i] = v0 ? *(const float4*)&row0[4 * lane + 128 * i] : make_float4(0,0,0,0);
            xv1[i] = v1 ? *(const float4*)&row1[4 * lane + 128 * i] : make_float4(0,0,0,0);
        }

        // matvec: 16 outputs for both nodes, Wc2 loaded once per pair
        float acc0[16], acc1[16];
        #pragma unroll
        for (int o = 0; o < 16; o++) {
            float a0 = 0.f, a1 = 0.f;
            #pragma unroll
            for (int i = 0; i < 4; i++) {
                float4 wv = *(const float4*)&g_Wc2[o * 512 + 4 * lane + 128 * i];
                a0 += xv0[i].x * wv.x + xv0[i].y * wv.y + xv0[i].z * wv.z + xv0[i].w * wv.w;
                a1 += xv1[i].x * wv.x + xv1[i].y * wv.y + xv1[i].z * wv.z + xv1[i].w * wv.w;
            }
            acc0[o] = a0; acc1[o] = a1;
        }

        // vector butterfly reduction: fold 16-vec over lanes, 4 steps + xor-16
        #pragma unroll
        for (int s = 0; s < 4; s++) {
            const int d = 1 << s;
            const int m2 = 8 >> s;
            bool up = (lane & d) != 0;
            #pragma unroll
            for (int j = 0; j < m2; j++) {
                float mine0 = up ? acc0[j + m2] : acc0[j];
                float send0 = up ? acc0[j] : acc0[j + m2];
                acc0[j] = mine0 + __shfl_xor_sync(0xffffffffu, send0, d);
                float mine1 = up ? acc1[j + m2] : acc1[j];
                float send1 = up ? acc1[j] : acc1[j + m2];
                acc1[j] = mine1 + __shfl_xor_sync(0xffffffffu, send1, d);
            }
        }
        acc0[0] += __shfl_xor_sync(0xffffffffu, acc0[0], 16);
        acc1[0] += __shfl_xor_sync(0xffffffffu, acc1[0], 16);

        // lane -> output index: o = 8*b0 + 4*b1 + 2*b2 + 1*b3 (bit-reversed nibble)
        int lo = lane & 15;
        int o = ((lo & 1) << 3) | ((lo & 2) << 1) | ((lo & 4) >> 1) | ((lo & 8) >> 3);

        if (lane < 16) {
            if (v0) {
                float xc = acc0[0] + g_bc2[o];
                g_z[(size_t)n0 * 48 + o] = xc;
                atomicAdd(&sh_s[o], xc);
                atomicAdd(&sh_q[o], xc * xc);
            }
        } else {
            if (v1) {
                float xc = acc1[0] + g_bc2[o];
                g_z[(size_t)n1 * 48 + o] = xc;
                atomicAdd(&sh_s[o], xc);
                atomicAdd(&sh_q[o], xc * xc);
            }
        }
        if (v0) g_z[(size_t)n0 * 48 + 16 + lane] = fn0;
        if (v1) g_z[(size_t)n1 * 48 + 16 + lane] = fn1;
        atomicAdd(&sh_s[16 + lane], fn0 + fn1);
        atomicAdd(&sh_q[16 + lane], fn0 * fn0 + fn1 * fn1);
        __syncthreads();
        if (tid < 48) { atomicAdd(&g_sum2[tid], sh_s[tid]); atomicAdd(&g_sumsq2[tid], sh_q[tid]); }
    }
}

// ---- merged: fold bn2 into Wp (blocks 0..63) | CSR scatter (blocks 64+) -----
__global__ void k_fold2_scatter(const float* __restrict__ Wp, const float* __restrict__ bp,
                                const float* __restrict__ bn2_g, const float* __restrict__ bn2_b,
                                const int* __restrict__ ei) {
    int b = blockIdx.x, t = threadIdx.x;  // 256 threads
    if (b < 64) {
        __shared__ float red[256];
        float p = 0.f;
        if (t < 48) {
            const float invN = 1.f / Nn;
            float mean = g_sum2[t] * invN;
            float var  = g_sumsq2[t] * invN - mean * mean;
            float r = rsqrtf(var + EPS);
            float sc = r * bn2_g[t];
            float sh = bn2_b[t] - mean * sc;
            float w = Wp[b * 48 + t];
            g_Wp2[b * 48 + t] = w * sc;
            p = w * sh;
        }
        red[t] = p;
        __syncthreads();
        for (int s = 128; s; s >>= 1) { if (t < s) red[t] += red[t + s]; __syncthreads(); }
        if (t == 0) g_bp2[b] = bp[b] + red[0];
    } else {
        int e = (b - 64) * 256 + t;
        int di = ei[Ee + e];
        int pos = atomicAdd(&g_cursor[di], 1);
        g_col[pos] = ei[e];
    }
}

// --------------- per node: t = relu(Wp2 z + bp2), plus attention logits -----
__global__ void k_node_t() {
    __shared__ float wp[64 * 49];
    __shared__ float zb[8][48];
    int tid = threadIdx.x;
    for (int i = tid; i < 64 * 48; i += 256) {
        int o = i / 48, k = i - o * 48;
        wp[o * 49 + k] = g_Wp2[i];
    }
    __syncthreads();
    int w = tid >> 5, lane = tid & 31;
    int n = blockIdx.x * 8 + w;
    const float* zr = g_z + (size_t)n * 48;
    zb[w][lane] = zr[lane];
    if (lane < 16) zb[w][32 + lane] = zr[32 + lane];
    __syncwarp();
    float t0 = g_bp2[lane], t1 = g_bp2[lane + 32];
    #pragma unroll
    for (int k = 0; k < 48; k++) {
        float zv = zb[w][k];
        t0 += wp[lane * 49 + k] * zv;
        t1 += wp[(lane + 32) * 49 + k] * zv;
    }
    t0 = fmaxf(t0, 0.f);
    t1 = fmaxf(t1, 0.f);
    ((float2*)g_t)[(size_t)n * 32 + lane] = make_float2(t0, t1);

    #pragma unroll
    for (int hd = 0; hd < 4; hd++) {
        float ps = t0 * g_wsrc[hd * 64 + lane] + t1 * g_wsrc[hd * 64 + 32 + lane];
        float pd = t0 * g_wdst[hd * 64 + lane] + t1 * g_wdst[hd * 64 + 32 + lane];
        float vs = warp_sum(ps);
        float vd = warp_sum(pd);
        if (lane == 0) { g_asrc[n * 4 + hd] = vs; g_adst[n * 4 + hd] = vd; }
    }
}

// --------- fused softmax + aggregation in t-space: warp per dst node --------
__global__ void k_agg() {
    int tid = threadIdx.x;
    int w = tid >> 5, lane = tid & 31;
    int n = blockIdx.x * 8 + w;
    int r0 = g_rowptr[n], r1 = g_rowptr[n + 1];
    float4 ad = *(const float4*)&g_adst[n * 4];
    const float2* t2 = (const float2*)g_t;

    float acc[8];
    #pragma unroll
    for (int i = 0; i < 8; i++) acc[i] = 0.f;
    float s0 = 0.f, s1 = 0.f, s2 = 0.f, s3 = 0.f;

    for (int base = r0; base < r1; base += 32) {
        int cnt = min(32, r1 - base);
        int si = 0;
        float ex0 = 0.f, ex1 = 0.f, ex2 = 0.f, ex3 = 0.f;
        if (lane < cnt) {
            si = g_col[base + lane];
            float4 as = *(const float4*)&g_asrc[si * 4];
            float e0 = as.x + ad.x, e1 = as.y + ad.y, e2 = as.z + ad.z, e3 = as.w + ad.w;
            e0 = e0 > 0.f ? e0 : 0.2f * e0;
            e1 = e1 > 0.f ? e1 : 0.2f * e1;
            e2 = e2 > 0.f ? e2 : 0.2f * e2;
            e3 = e3 > 0.f ? e3 : 0.2f * e3;
            ex0 = __expf(e0); ex1 = __expf(e1); ex2 = __expf(e2); ex3 = __expf(e3);
            s0 += ex0; s1 += ex1; s2 += ex2; s3 += ex3;
        }
        for (int j = 0; j < cnt; j++) {
            int sj   = __shfl_sync(0xffffffffu, si, j);
            float a0 = __shfl_sync(0xffffffffu, ex0, j);
            float a1 = __shfl_sync(0xffffffffu, ex1, j);
            float a2 = __shfl_sync(0xffffffffu, ex2, j);
            float a3 = __shfl_sync(0xffffffffu, ex3, j);
            float2 u = t2[(size_t)sj * 32 + lane];
            acc[0] += a0 * u.x; acc[1] += a0 * u.y;
            acc[2] += a1 * u.x; acc[3] += a1 * u.y;
            acc[4] += a2 * u.x; acc[5] += a2 * u.y;
            acc[6] += a3 * u.x; acc[7] += a3 * u.y;
        }
    }
    s0 = warp_sum(s0); s1 = warp_sum(s1); s2 = warp_sum(s2); s3 = warp_sum(s3);
    float i0 = 1.f / fmaxf(s0, 1e-16f);
    float i1 = 1.f / fmaxf(s1, 1e-16f);
    float i2 = 1.f / fmaxf(s2, 1e-16f);
    float i3 = 1.f / fmaxf(s3, 1e-16f);
    float* o = g_aggt + (size_t)n * 256;
    o[lane]            = acc[0] * i0;  o[lane + 32]       = acc[1] * i0;
    o[64 + lane]       = acc[2] * i1;  o[64 + 32 + lane]  = acc[3] * i1;
    o[128 + lane]      = acc[4] * i2;  o[128 + 32 + lane] = acc[5] * i2;
    o[192 + lane]      = acc[6] * i3;  o[192 + 32 + lane] = acc[7] * i3;
}

// -------- GEMM: out[:, hd] = aggt[:, hd] @ Wg[hd]^T + reduced bn3 stats ------
__global__ void k_gemm_out(const float* __restrict__ Wg) {
    __shared__ float tsh[64 * 68];
    __shared__ float wsh[64 * 68];
    int n0 = blockIdx.x * 64;
    int hd = blockIdx.y;
    int out0 = hd * 64;
    int tid = threadIdx.x;

    for (int i = tid; i < 64 * 16; i += 256) {
        int r = i >> 4, c = (i & 15) << 2;
        float4 v = make_float4(0.f, 0.f, 0.f, 0.f);
        int n = n0 + r;
        if (n < Nn) v = *(const float4*)&g_aggt[(size_t)n * 256 + out0 + c];
        *(float4*)&tsh[r * 68 + c] = v;
        float4 wv = *(const float4*)&Wg[(size_t)(out0 + r) * 64 + c];
        *(float4*)&wsh[r * 68 + c] = wv;
    }
    __syncthreads();

    int tx = tid & 31, ty = tid >> 5;
    float acc[8][2];
    #pragma unroll
    for (int i = 0; i < 8; i++) { acc[i][0] = 0.f; acc[i][1] = 0.f; }

    #pragma unroll 4
    for (int k = 0; k < 64; k += 4) {
        float4 tv[8], wv[2];
        #pragma unroll
        for (int i = 0; i < 8; i++) tv[i] = *(float4*)&tsh[(ty * 8 + i) * 68 + k];
        wv[0] = *(float4*)&wsh[tx * 68 + k];
        wv[1] = *(float4*)&wsh[(tx + 32) * 68 + k];
        #pragma unroll
        for (int i = 0; i < 8; i++) {
            #pragma unroll
            for (int o = 0; o < 2; o++) {
                acc[i][o] += tv[i].x * wv[o].x;
                acc[i][o] += tv[i].y * wv[o].y;
                acc[i][o] += tv[i].z * wv[o].z;
                acc[i][o] += tv[i].w * wv[o].w;
            }
        }
    }
    float ps0 = 0.f, pq0 = 0.f, ps1 = 0.f, pq1 = 0.f;
    #pragma unroll
    for (int i = 0; i < 8; i++) {
        int n = n0 + ty * 8 + i;
        if (n < Nn) {
            g_out[(size_t)n * 256 + out0 + tx]      = acc[i][0];
            g_out[(size_t)n * 256 + out0 + tx + 32] = acc[i][1];
            ps0 += acc[i][0]; pq0 += acc[i][0] * acc[i][0];
            ps1 += acc[i][1]; pq1 += acc[i][1] * acc[i][1];
        }
    }
    __syncthreads();
    tsh[ty * 32 + tx]       = ps0;
    tsh[256 + ty * 32 + tx] = pq0;
    tsh[512 + ty * 32 + tx] = ps1;
    tsh[768 + ty * 32 + tx] = pq1;
    __syncthreads();
    if (ty == 0) {
        float a0 = 0.f, a1 = 0.f, a2 = 0.f, a3 = 0.f;
        #pragma unroll
        for (int j = 0; j < 8; j++) {
            a0 += tsh[j * 32 + tx];
            a1 += tsh[256 + j * 32 + tx];
            a2 += tsh[512 + j * 32 + tx];
            a3 += tsh[768 + j * 32 + tx];
        }
        atomicAdd(&g_sum3[out0 + tx], a0);
        atomicAdd(&g_sumsq3[out0 + tx], a1);
        atomicAdd(&g_sum3[out0 + tx + 32], a2);
        atomicAdd(&g_sumsq3[out0 + tx + 32], a3);
    }
}

// -------- per-group: bn3 + elu + mean-pool (contiguous, no atomics) + head --
__global__ void k_pool_head(const float* __restrict__ bn3_g, const float* __restrict__ bn3_b,
                            const float* __restrict__ W1, const float* __restrict__ b1,
                            const float* __restrict__ W2, const float* __restrict__ b2,
                            float* __restrict__ out) {
    __shared__ float p[256];
    __shared__ float hm[64];
    int g = blockIdx.x, c = threadIdx.x;
    const float invN = 1.f / Nn;
    float mean = g_sum3[c] * invN;
    float var  = g_sumsq3[c] * invN - mean * mean;
    float r = rsqrtf(var + EPS);
    float sc = r * bn3_g[c];
    float sh = bn3_b[c] - mean * sc;
    int r0 = g_gptr[g], r1 = g_gptr[g + 1];
    float s = 0.f;
    for (int n = r0; n < r1; n++) {
        float v = g_out[(size_t)n * 256 + c] * sc + sh;
        v = v > 0.f ? v : (__expf(v) - 1.f);
        s += v;
    }
    p[c] = s / fmaxf((float)(r1 - r0), 1.f);
    __syncthreads();
    if (c < 64) {
        float a = b1[c];
        #pragma unroll 8
        for (int k = 0; k < 256; k++) a += p[k] * W1[c * 256 + k];
        hm[c] = fmaxf(a, 0.f);
    }
    __syncthreads();
    if (c < 2) {
        float a = b2[c];
        #pragma unroll
        for (int k = 0; k < 64; k++) a += hm[k] * W2[c * 64 + k];
        out[g * 2 + c] = a;
    }
}

// ------------------------- launch ---------------------------------------------
extern "C" void kernel_launch(void* const* d_in, const int* in_sizes, int n_in,
                              void* d_out, int out_size) {
    const float* x       = (const float*)d_in[0];
    const int*   ei      = (const int*)d_in[1];
    const int*   batch   = (const int*)d_in[2];
    const float* ln_g    = (const float*)d_in[3];
    const float* ln_b    = (const float*)d_in[4];
    const float* bn1_g   = (const float*)d_in[5];
    const float* bn1_b   = (const float*)d_in[6];
    const float* Wc      = (const float*)d_in[7];
    const float* bc      = (const float*)d_in[8];
    const float* bn2_g   = (const float*)d_in[9];
    const float* bn2_b   = (const float*)d_in[10];
    const float* Wp      = (const float*)d_in[11];
    const float* bp      = (const float*)d_in[12];
    const float* Wg      = (const float*)d_in[13];
    const float* att_src = (const float*)d_in[14];
    const float* att_dst = (const float*)d_in[15];
    // d_in[16] = bg : cancels under bn3 (pure mean shift) -> unused
    const float* bn3_g   = (const float*)d_in[17];
    const float* bn3_b   = (const float*)d_in[18];
    const float* W1      = (const float*)d_in[19];
    const float* b1      = (const float*)d_in[20];
    const float* W2      = (const float*)d_in[21];
    const float* b2      = (const float*)d_in[22];
    float* out = (float*)d_out;

    k_init<<<200, 256>>>(Wg, att_src, att_dst);
    k_pre<<<B_STATS + B_DEG + B_BP, 512>>>(x, ei, batch);
    k_fold_scan1<<<16 + NCH, 512>>>(Wc, bc, bn1_g, bn1_b);
    k_scan3_nodez<<<NCH + B_NZ, 512>>>(x, ln_g, ln_b);
    k_fold2_scatter<<<64 + 3125, 256>>>(Wp, bp, bn2_g, bn2_b, ei);
    k_node_t<<<6250, 256>>>();
    k_agg<<<6250, 256>>>();
    dim3 gh(782, 4);
    k_gemm_out<<<gh, 256>>>(Wg);
    k_pool_head<<<Gg, 256>>>(bn3_g, bn3_b, W1, b1, W2, b2, out);
}

// round 9
// speedup vs baseline: 1.2271x; 1.0501x over previous
#include <cuda_runtime.h>
#include <math.h>
#include <stdint.h>

#define Nn 50000
#define Ee 800000
#define Gg 512
#define EPS 1e-5f
#define NCH 196           // chunks of 256 for CSR scan
#define B_STATS 1000
#define B_DEG   1563      // ceil(800000/512)
#define B_BP    98        // ceil(50000/512)
#define B_NZ    3125      // nodez blocks (16 nodes each, 256 thr)

// ------------------------- device scratch (static, no allocs) ---------------
__device__ float g_sum1[512], g_sumsq1[512];
__device__ __align__(16) float g_Wc2[16 * 512];
__device__ float g_bc2[16];
__device__ __align__(16) float g_z[(size_t)Nn * 48];
__device__ float g_sum2[48], g_sumsq2[48];
__device__ float g_Wp2[64 * 48], g_bp2[64];
__device__ __align__(16) float g_t[(size_t)Nn * 64];   // interleaved (k, k+32) float2
__device__ float g_wsrc[4 * 64], g_wdst[4 * 64];
__device__ __align__(16) float g_asrc[Nn * 4];
__device__ __align__(16) float g_adst[Nn * 4];
__device__ int g_deg[Nn];
__device__ int g_rowptr[Nn + 1];
__device__ int g_cursor[Nn];
__device__ int g_chunksum[NCH];
__device__ int g_col[Ee];
__device__ int g_gptr[Gg + 1];
__device__ __align__(16) float g_aggt[(size_t)Nn * 256];
__device__ __align__(16) float g_out[(size_t)Nn * 256];
__device__ float g_sum3[256], g_sumsq3[256];

// ------------------------- helpers ------------------------------------------
__device__ __forceinline__ float warp_sum(float v) {
    #pragma unroll
    for (int off = 16; off; off >>= 1) v += __shfl_xor_sync(0xffffffffu, v, off);
    return v;
}
__device__ __forceinline__ int warp_sum_i(int v) {
    #pragma unroll
    for (int off = 16; off; off >>= 1) v += __shfl_xor_sync(0xffffffffu, v, off);
    return v;
}

// ------- init (per-launch reset) + att-vector fold (no dependencies) --------
__global__ void k_init(const float* __restrict__ Wg,
                       const float* __restrict__ att_src, const float* __restrict__ att_dst) {
    int b = blockIdx.x, t = threadIdx.x;
    if (b < 196) {
        int i = b * 256 + t;
        int stride = 196 * 256;
        for (int j = i; j < Nn; j += stride) g_deg[j] = 0;
        if (i < 512) { g_sum1[i] = 0.f; g_sumsq1[i] = 0.f; }
        if (i < 256) { g_sum3[i] = 0.f; g_sumsq3[i] = 0.f; }
        if (i < 48)  { g_sum2[i] = 0.f; g_sumsq2[i] = 0.f; }
    } else {
        int hd = b - 196;
        __shared__ float as[64], ad[64];
        if (t < 64) { as[t] = att_src[hd * 64 + t]; ad[t] = att_dst[hd * 64 + t]; }
        __syncthreads();
        if (t < 64) {
            float s = 0.f, d = 0.f;
            #pragma unroll 8
            for (int j = 0; j < 64; j++) {
                float w = Wg[(size_t)(hd * 64 + j) * 64 + t];
                s += as[j] * w;
                d += ad[j] * w;
            }
            g_wsrc[hd * 64 + t] = s;
            g_wdst[hd * 64 + t] = d;
        }
    }
}

// ---- merged: bn1 stats | degree count | batch group boundaries --------------
__global__ void k_pre(const float* __restrict__ x, const int* __restrict__ ei,
                      const int* __restrict__ batch) {
    int b = blockIdx.x;
    if (b < B_STATS) {
        int c = threadIdx.x;  // 512 threads
        float s = 0.f, q = 0.f;
        for (int r = b; r < Nn; r += B_STATS) {
            float v = x[(size_t)r * 544 + c];
            s += v; q += v * v;
        }
        atomicAdd(&g_sum1[c], s);
        atomicAdd(&g_sumsq1[c], q);
    } else if (b < B_STATS + B_DEG) {
        int e = (b - B_STATS) * 512 + threadIdx.x;
        if (e < Ee) atomicAdd(&g_deg[ei[Ee + e]], 1);
    } else {
        int n = (b - B_STATS - B_DEG) * 512 + threadIdx.x;
        if (n < Nn) {
            int bb = batch[n];
            int prev = (n == 0) ? -1 : batch[n - 1];
            for (int g = prev + 1; g <= bb; g++) g_gptr[g] = n;
            if (n == Nn - 1) for (int g = bb + 1; g <= Gg; g++) g_gptr[g] = Nn;
        }
    }
}

// ---- merged: fold bn1 into Wc (blocks 0..15) | scan1: 2x256-chunk sums -----
__global__ void k_fold_scan1(const float* __restrict__ Wc, const float* __restrict__ bc,
                             const float* __restrict__ bn1_g, const float* __restrict__ bn1_b) {
    int b = blockIdx.x, t = threadIdx.x;  // 512 threads
    if (b < 16) {
        __shared__ float red[512];
        const float invN = 1.f / Nn;
        float mean = g_sum1[t] * invN;
        float var  = g_sumsq1[t] * invN - mean * mean;
        float r = rsqrtf(var + EPS);
        float sc = r * bn1_g[t];
        float sh = bn1_b[t] - mean * sc;
        float w = Wc[b * 512 + t];
        g_Wc2[b * 512 + t] = w * sc;
        red[t] = w * sh;
        __syncthreads();
        for (int s = 256; s; s >>= 1) { if (t < s) red[t] += red[t + s]; __syncthreads(); }
        if (t == 0) g_bc2[b] = bc[b] + red[0];
    } else {
        int cpair = b - 16;            // 0..97, covers chunks 2*cpair, 2*cpair+1
        int idx = cpair * 512 + t;
        int d = (idx < Nn) ? g_deg[idx] : 0;
        int s = warp_sum_i(d);
        __shared__ int sh[16];
        if ((t & 31) == 0) sh[t >> 5] = s;
        __syncthreads();
        if (t == 0) {
            int a = 0;
            #pragma unroll
            for (int i = 0; i < 8; i++) a += sh[i];
            g_chunksum[cpair * 2] = a;
        } else if (t == 256) {
            int a = 0;
            #pragma unroll
            for (int i = 8; i < 16; i++) a += sh[i];
            g_chunksum[cpair * 2 + 1] = a;
        }
    }
}

// ---- merged: scan phase 2+3 (blocks 0..195) | node_z 2/warp (196+) ---------
__global__ void k_scan3_nodez(const float* __restrict__ x,
                              const float* __restrict__ ln_g, const float* __restrict__ ln_b) {
    int b = blockIdx.x, tid = threadIdx.x;  // 256 threads
    if (b < NCH) {
        __shared__ int sh[256];
        __shared__ int ssum[8];
        __shared__ int off_s;
        int v = (tid < b) ? g_chunksum[tid] : 0;
        v = warp_sum_i(v);
        if ((tid & 31) == 0) ssum[tid >> 5] = v;
        __syncthreads();
        if (tid == 0) {
            int o = 0;
            #pragma unroll
            for (int i = 0; i < 8; i++) o += ssum[i];
            off_s = o;
        }
        int idx = b * 256 + tid;
        int d = (idx < Nn) ? g_deg[idx] : 0;
        sh[tid] = d;
        __syncthreads();
        for (int off = 1; off < 256; off <<= 1) {
            int u = (tid >= off) ? sh[tid - off] : 0;
            __syncthreads();
            sh[tid] += u;
            __syncthreads();
        }
        if (idx < Nn) {
            int pos = off_s + sh[tid] - d;
            g_rowptr[idx] = pos;
            g_cursor[idx] = pos;
        }
        if (idx == Nn - 1) g_rowptr[Nn] = Ee;
    } else {
        __shared__ float sh_s[48], sh_q[48];
        if (tid < 48) { sh_s[tid] = 0.f; sh_q[tid] = 0.f; }
        __syncthreads();
        int w = tid >> 5, lane = tid & 31;
        int n0 = (b - NCH) * 16 + w * 2;   // exact: 3125*16 = 50000
        int n1 = n0 + 1;
        const float* row0 = x + (size_t)n0 * 544;
        const float* row1 = x + (size_t)n1 * 544;

        // layernorm on f for both nodes
        float fv0 = row0[512 + lane];
        float mu0 = warp_sum(fv0) * (1.f / 32.f);
        float qq0 = warp_sum(fv0 * fv0) * (1.f / 32.f);
        float fn0 = (fv0 - mu0) * rsqrtf(qq0 - mu0 * mu0 + EPS) * ln_g[lane] + ln_b[lane];
        float fv1 = row1[512 + lane];
        float mu1 = warp_sum(fv1) * (1.f / 32.f);
        float qq1 = warp_sum(fv1 * fv1) * (1.f / 32.f);
        float fn1 = (fv1 - mu1) * rsqrtf(qq1 - mu1 * mu1 + EPS) * ln_g[lane] + ln_b[lane];

        // load x rows (vectorized)
        float4 xv0[4], xv1[4];
        #pragma unroll
        for (int i = 0; i < 4; i++) {
            xv0[i] = *(const float4*)&row0[4 * lane + 128 * i];
            xv1[i] = *(const float4*)&row1[4 * lane + 128 * i];
        }

        // matvec: 16 outputs for both nodes, Wc2 loaded once per pair
        float acc0[16], acc1[16];
        #pragma unroll
        for (int o = 0; o < 16; o++) {
            float a0 = 0.f, a1 = 0.f;
            #pragma unroll
            for (int i = 0; i < 4; i++) {
                float4 wv = *(const float4*)&g_Wc2[o * 512 + 4 * lane + 128 * i];
                a0 += xv0[i].x * wv.x + xv0[i].y * wv.y + xv0[i].z * wv.z + xv0[i].w * wv.w;
                a1 += xv1[i].x * wv.x + xv1[i].y * wv.y + xv1[i].z * wv.z + xv1[i].w * wv.w;
            }
            acc0[o] = a0; acc1[o] = a1;
        }

        // vector butterfly reduction: fold 16-vec over lanes, 4 steps + xor-16
        #pragma unroll
        for (int s = 0; s < 4; s++) {
            const int d = 1 << s;
            const int m2 = 8 >> s;
            bool up = (lane & d) != 0;
            #pragma unroll
            for (int j = 0; j < m2; j++) {
                float mine0 = up ? acc0[j + m2] : acc0[j];
                float send0 = up ? acc0[j] : acc0[j + m2];
                acc0[j] = mine0 + __shfl_xor_sync(0xffffffffu, send0, d);
                float mine1 = up ? acc1[j + m2] : acc1[j];
                float send1 = up ? acc1[j] : acc1[j + m2];
                acc1[j] = mine1 + __shfl_xor_sync(0xffffffffu, send1, d);
            }
        }
        acc0[0] += __shfl_xor_sync(0xffffffffu, acc0[0], 16);
        acc1[0] += __shfl_xor_sync(0xffffffffu, acc1[0], 16);

        // lane -> output index (bit-reversed nibble)
        int lo = lane & 15;
        int o = ((lo & 1) << 3) | ((lo & 2) << 1) | ((lo & 4) >> 1) | ((lo & 8) >> 3);

        if (lane < 16) {
            float xc = acc0[0] + g_bc2[o];
            g_z[(size_t)n0 * 48 + o] = xc;
            atomicAdd(&sh_s[o], xc);
            atomicAdd(&sh_q[o], xc * xc);
        } else {
            float xc = acc1[0] + g_bc2[o];
            g_z[(size_t)n1 * 48 + o] = xc;
            atomicAdd(&sh_s[o], xc);
            atomicAdd(&sh_q[o], xc * xc);
        }
        g_z[(size_t)n0 * 48 + 16 + lane] = fn0;
        g_z[(size_t)n1 * 48 + 16 + lane] = fn1;
        atomicAdd(&sh_s[16 + lane], fn0 + fn1);
        atomicAdd(&sh_q[16 + lane], fn0 * fn0 + fn1 * fn1);
        __syncthreads();
        if (tid < 48) { atomicAdd(&g_sum2[tid], sh_s[tid]); atomicAdd(&g_sumsq2[tid], sh_q[tid]); }
    }
}

// ---- merged: fold bn2 into Wp (blocks 0..63) | CSR scatter (blocks 64+) -----
__global__ void k_fold2_scatter(const float* __restrict__ Wp, const float* __restrict__ bp,
                                const float* __restrict__ bn2_g, const float* __restrict__ bn2_b,
                                const int* __restrict__ ei) {
    int b = blockIdx.x, t = threadIdx.x;  // 256 threads
    if (b < 64) {
        __shared__ float red[256];
        float p = 0.f;
        if (t < 48) {
            const float invN = 1.f / Nn;
            float mean = g_sum2[t] * invN;
            float var  = g_sumsq2[t] * invN - mean * mean;
            float r = rsqrtf(var + EPS);
            float sc = r * bn2_g[t];
            float sh = bn2_b[t] - mean * sc;
            float w = Wp[b * 48 + t];
            g_Wp2[b * 48 + t] = w * sc;
            p = w * sh;
        }
        red[t] = p;
        __syncthreads();
        for (int s = 128; s; s >>= 1) { if (t < s) red[t] += red[t + s]; __syncthreads(); }
        if (t == 0) g_bp2[b] = bp[b] + red[0];
    } else {
        int e = (b - 64) * 256 + t;
        int di = ei[Ee + e];
        int pos = atomicAdd(&g_cursor[di], 1);
        g_col[pos] = ei[e];
    }
}

// --------------- per node: t = relu(Wp2 z + bp2), plus attention logits -----
__global__ void k_node_t() {
    __shared__ float wp[64 * 49];
    __shared__ float zb[8][48];
    int tid = threadIdx.x;
    for (int i = tid; i < 64 * 48; i += 256) {
        int o = i / 48, k = i - o * 48;
        wp[o * 49 + k] = g_Wp2[i];
    }
    __syncthreads();
    int w = tid >> 5, lane = tid & 31;
    int n = blockIdx.x * 8 + w;
    const float* zr = g_z + (size_t)n * 48;
    zb[w][lane] = zr[lane];
    if (lane < 16) zb[w][32 + lane] = zr[32 + lane];
    __syncwarp();
    float t0 = g_bp2[lane], t1 = g_bp2[lane + 32];
    #pragma unroll
    for (int k = 0; k < 48; k++) {
        float zv = zb[w][k];
        t0 += wp[lane * 49 + k] * zv;
        t1 += wp[(lane + 32) * 49 + k] * zv;
    }
    t0 = fmaxf(t0, 0.f);
    t1 = fmaxf(t1, 0.f);
    ((float2*)g_t)[(size_t)n * 32 + lane] = make_float2(t0, t1);

    #pragma unroll
    for (int hd = 0; hd < 4; hd++) {
        float ps = t0 * g_wsrc[hd * 64 + lane] + t1 * g_wsrc[hd * 64 + 32 + lane];
        float pd = t0 * g_wdst[hd * 64 + lane] + t1 * g_wdst[hd * 64 + 32 + lane];
        float vs = warp_sum(ps);
        float vd = warp_sum(pd);
        if (lane == 0) { g_asrc[n * 4 + hd] = vs; g_adst[n * 4 + hd] = vd; }
    }
}

// --------- fused softmax + aggregation in t-space: warp per dst node --------
__global__ void k_agg() {
    int tid = threadIdx.x;
    int w = tid >> 5, lane = tid & 31;
    int n = blockIdx.x * 8 + w;
    int r0 = g_rowptr[n], r1 = g_rowptr[n + 1];
    float4 ad = *(const float4*)&g_adst[n * 4];
    const float2* t2 = (const float2*)g_t;

    float acc[8];
    #pragma unroll
    for (int i = 0; i < 8; i++) acc[i] = 0.f;
    float s0 = 0.f, s1 = 0.f, s2 = 0.f, s3 = 0.f;

    for (int base = r0; base < r1; base += 32) {
        int cnt = min(32, r1 - base);
        int si = 0;
        float ex0 = 0.f, ex1 = 0.f, ex2 = 0.f, ex3 = 0.f;
        if (lane < cnt) {
            si = g_col[base + lane];
            float4 as = *(const float4*)&g_asrc[si * 4];
            float e0 = as.x + ad.x, e1 = as.y + ad.y, e2 = as.z + ad.z, e3 = as.w + ad.w;
            e0 = e0 > 0.f ? e0 : 0.2f * e0;
            e1 = e1 > 0.f ? e1 : 0.2f * e1;
            e2 = e2 > 0.f ? e2 : 0.2f * e2;
            e3 = e3 > 0.f ? e3 : 0.2f * e3;
            ex0 = __expf(e0); ex1 = __expf(e1); ex2 = __expf(e2); ex3 = __expf(e3);
            s0 += ex0; s1 += ex1; s2 += ex2; s3 += ex3;
        }
        for (int j = 0; j < cnt; j++) {
            int sj   = __shfl_sync(0xffffffffu, si, j);
            float a0 = __shfl_sync(0xffffffffu, ex0, j);
            float a1 = __shfl_sync(0xffffffffu, ex1, j);
            float a2 = __shfl_sync(0xffffffffu, ex2, j);
            float a3 = __shfl_sync(0xffffffffu, ex3, j);
            float2 u = t2[(size_t)sj * 32 + lane];
            acc[0] += a0 * u.x; acc[1] += a0 * u.y;
            acc[2] += a1 * u.x; acc[3] += a1 * u.y;
            acc[4] += a2 * u.x; acc[5] += a2 * u.y;
            acc[6] += a3 * u.x; acc[7] += a3 * u.y;
        }
    }
    s0 = warp_sum(s0); s1 = warp_sum(s1); s2 = warp_sum(s2); s3 = warp_sum(s3);
    float i0 = 1.f / fmaxf(s0, 1e-16f);
    float i1 = 1.f / fmaxf(s1, 1e-16f);
    float i2 = 1.f / fmaxf(s2, 1e-16f);
    float i3 = 1.f / fmaxf(s3, 1e-16f);
    float* o = g_aggt + (size_t)n * 256;
    o[lane]            = acc[0] * i0;  o[lane + 32]       = acc[1] * i0;
    o[64 + lane]       = acc[2] * i1;  o[64 + 32 + lane]  = acc[3] * i1;
    o[128 + lane]      = acc[4] * i2;  o[128 + 32 + lane] = acc[5] * i2;
    o[192 + lane]      = acc[6] * i3;  o[192 + 32 + lane] = acc[7] * i3;
}

// -------- GEMM: out[:, hd] = aggt[:, hd] @ Wg[hd]^T + reduced bn3 stats ------
// tile 128 nodes x 64 outs, thread 8x4, transposed smem (broadcast-friendly)
__global__ void k_gemm_out(const float* __restrict__ Wg) {
    __shared__ float xs[32 * 132];   // xs[k][n]
    __shared__ float ws[32 * 68];    // ws[k][o]
    __shared__ float rs[64 * 16];
    __shared__ float rq[64 * 16];
    int n0 = blockIdx.x * 128;
    int hd = blockIdx.y, out0 = hd * 64;
    int tid = threadIdx.x;           // 256
    int tx = tid & 15, ty = tid >> 4;

    float acc[8][4];
    #pragma unroll
    for (int i = 0; i < 8; i++)
        #pragma unroll
        for (int o = 0; o < 4; o++) acc[i][o] = 0.f;

    #pragma unroll
    for (int kc = 0; kc < 2; kc++) {
        int kb = kc * 32;
        if (kc) __syncthreads();
        #pragma unroll
        for (int ii = 0; ii < 4; ii++) {
            int i = tid + ii * 256;
            int nr = i >> 3, c4 = (i & 7) << 2;
            float4 v = make_float4(0.f, 0.f, 0.f, 0.f);
            int n = n0 + nr;
            if (n < Nn) v = *(const float4*)&g_aggt[(size_t)n * 256 + out0 + kb + c4];
            xs[(c4 + 0) * 132 + nr] = v.x;
            xs[(c4 + 1) * 132 + nr] = v.y;
            xs[(c4 + 2) * 132 + nr] = v.z;
            xs[(c4 + 3) * 132 + nr] = v.w;
        }
        #pragma unroll
        for (int ii = 0; ii < 2; ii++) {
            int i = tid + ii * 256;
            int orow = i >> 3, c4 = (i & 7) << 2;
            float4 v = *(const float4*)&Wg[(size_t)(out0 + orow) * 64 + kb + c4];
            ws[(c4 + 0) * 68 + orow] = v.x;
            ws[(c4 + 1) * 68 + orow] = v.y;
            ws[(c4 + 2) * 68 + orow] = v.z;
            ws[(c4 + 3) * 68 + orow] = v.w;
        }
        __syncthreads();
        #pragma unroll
        for (int k = 0; k < 32; k++) {
            float4 wv = *(float4*)&ws[k * 68 + tx * 4];
            float4 x0 = *(float4*)&xs[k * 132 + ty * 8];
            float4 x1 = *(float4*)&xs[k * 132 + ty * 8 + 4];
            float xa[8] = {x0.x, x0.y, x0.z, x0.w, x1.x, x1.y, x1.z, x1.w};
            #pragma unroll
            for (int i = 0; i < 8; i++) {
                acc[i][0] += xa[i] * wv.x;
                acc[i][1] += xa[i] * wv.y;
                acc[i][2] += xa[i] * wv.z;
                acc[i][3] += xa[i] * wv.w;
            }
        }
    }
    float ps[4] = {0.f, 0.f, 0.f, 0.f}, pq[4] = {0.f, 0.f, 0.f, 0.f};
    #pragma unroll
    for (int i = 0; i < 8; i++) {
        int n = n0 + ty * 8 + i;
        if (n < Nn) {
            *(float4*)&g_out[(size_t)n * 256 + out0 + tx * 4] =
                make_float4(acc[i][0], acc[i][1], acc[i][2], acc[i][3]);
            #pragma unroll
            for (int o = 0; o < 4; o++) { ps[o] += acc[i][o]; pq[o] += acc[i][o] * acc[i][o]; }
        }
    }
    __syncthreads();
    #pragma unroll
    for (int o = 0; o < 4; o++) {
        rs[(tx * 4 + o) * 16 + ty] = ps[o];
        rq[(tx * 4 + o) * 16 + ty] = pq[o];
    }
    __syncthreads();
    if (tid < 64) {
        float a = 0.f, q = 0.f;
        #pragma unroll
        for (int j = 0; j < 16; j++) { a += rs[tid * 16 + j]; q += rq[tid * 16 + j]; }
        atomicAdd(&g_sum3[out0 + tid], a);
        atomicAdd(&g_sumsq3[out0 + tid], q);
    }
}

// -------- per-group: bn3 + elu + mean-pool (contiguous, no atomics) + head --
__global__ void k_pool_head(const float* __restrict__ bn3_g, const float* __restrict__ bn3_b,
                            const float* __restrict__ W1, const float* __restrict__ b1,
                            const float* __restrict__ W2, const float* __restrict__ b2,
                            float* __restrict__ out) {
    __shared__ float p[256];
    __shared__ float hm[64];
    int g = blockIdx.x, c = threadIdx.x;
    const float invN = 1.f / Nn;
    float mean = g_sum3[c] * invN;
    float var  = g_sumsq3[c] * invN - mean * mean;
    float r = rsqrtf(var + EPS);
    float sc = r * bn3_g[c];
    float sh = bn3_b[c] - mean * sc;
    int r0 = g_gptr[g], r1 = g_gptr[g + 1];
    float s = 0.f;
    for (int n = r0; n < r1; n++) {
        float v = g_out[(size_t)n * 256 + c] * sc + sh;
        v = v > 0.f ? v : (__expf(v) - 1.f);
        s += v;
    }
    p[c] = s / fmaxf((float)(r1 - r0), 1.f);
    __syncthreads();
    if (c < 64) {
        float a = b1[c];
        #pragma unroll 8
        for (int k = 0; k < 256; k++) a += p[k] * W1[c * 256 + k];
        hm[c] = fmaxf(a, 0.f);
    }
    __syncthreads();
    if (c < 2) {
        float a = b2[c];
        #pragma unroll
        for (int k = 0; k < 64; k++) a += hm[k] * W2[c * 64 + k];
        out[g * 2 + c] = a;
    }
}

// ------------------------- launch ---------------------------------------------
extern "C" void kernel_launch(void* const* d_in, const int* in_sizes, int n_in,
                              void* d_out, int out_size) {
    const float* x       = (const float*)d_in[0];
    const int*   ei      = (const int*)d_in[1];
    const int*   batch   = (const int*)d_in[2];
    const float* ln_g    = (const float*)d_in[3];
    const float* ln_b    = (const float*)d_in[4];
    const float* bn1_g   = (const float*)d_in[5];
    const float* bn1_b   = (const float*)d_in[6];
    const float* Wc      = (const float*)d_in[7];
    const float* bc      = (const float*)d_in[8];
    const float* bn2_g   = (const float*)d_in[9];
    const float* bn2_b   = (const float*)d_in[10];
    const float* Wp      = (const float*)d_in[11];
    const float* bp      = (const float*)d_in[12];
    const float* Wg      = (const float*)d_in[13];
    const float* att_src = (const float*)d_in[14];
    const float* att_dst = (const float*)d_in[15];
    // d_in[16] = bg : cancels under bn3 (pure mean shift) -> unused
    const float* bn3_g   = (const float*)d_in[17];
    const float* bn3_b   = (const float*)d_in[18];
    const float* W1      = (const float*)d_in[19];
    const float* b1      = (const float*)d_in[20];
    const float* W2      = (const float*)d_in[21];
    const float* b2      = (const float*)d_in[22];
    float* out = (float*)d_out;

    k_init<<<200, 256>>>(Wg, att_src, att_dst);
    k_pre<<<B_STATS + B_DEG + B_BP, 512>>>(x, ei, batch);
    k_fold_scan1<<<16 + 98, 512>>>(Wc, bc, bn1_g, bn1_b);
    k_scan3_nodez<<<NCH + B_NZ, 256>>>(x, ln_g, ln_b);
    k_fold2_scatter<<<64 + 3125, 256>>>(Wp, bp, bn2_g, bn2_b, ei);
    k_node_t<<<6250, 256>>>();
    k_agg<<<6250, 256>>>();
    dim3 gh(391, 4);
    k_gemm_out<<<gh, 256>>>(Wg);
    k_pool_head<<<Gg, 256>>>(bn3_g, bn3_b, W1, b1, W2, b2, out);
}

// round 10
// speedup vs baseline: 1.2631x; 1.0293x over previous
#include <cuda_runtime.h>
#include <math.h>
#include <stdint.h>

#define Nn 50000
#define Ee 800000
#define Gg 512
#define EPS 1e-5f
#define NCH 391           // chunks of 128 for CSR scan
#define B_STATS 1000
#define B_DEG   1563      // ceil(800000/512)
#define B_BP    98        // ceil(50000/512)
#define B_NZ    3125      // nodez blocks (16 nodes each, 128 thr, 4 warps x 4 nodes)

// ------------------------- device scratch (static, no allocs) ---------------
__device__ float g_sum1[512], g_sumsq1[512];
__device__ __align__(16) float g_Wc2[16 * 512];
__device__ float g_bc2[16];
__device__ __align__(16) float g_z[(size_t)Nn * 48];
__device__ float g_sum2[48], g_sumsq2[48];
__device__ float g_Wp2[64 * 48], g_bp2[64];
__device__ __align__(16) float g_t[(size_t)Nn * 64];   // interleaved (k, k+32) float2
__device__ float g_wsrc[4 * 64], g_wdst[4 * 64];
__device__ __align__(16) float g_asrc[Nn * 4];
__device__ __align__(16) float g_adst[Nn * 4];
__device__ int g_deg[Nn];
__device__ int g_rowptr[Nn + 1];
__device__ int g_cursor[Nn];
__device__ int g_chunksum[392];
__device__ int g_col[Ee];
__device__ int g_gptr[Gg + 1];
__device__ __align__(16) float g_aggt[(size_t)Nn * 256];
__device__ __align__(16) float g_out[(size_t)Nn * 256];
__device__ float g_sum3[256], g_sumsq3[256];

// ------------------------- helpers ------------------------------------------
__device__ __forceinline__ float warp_sum(float v) {
    #pragma unroll
    for (int off = 16; off; off >>= 1) v += __shfl_xor_sync(0xffffffffu, v, off);
    return v;
}
__device__ __forceinline__ int warp_sum_i(int v) {
    #pragma unroll
    for (int off = 16; off; off >>= 1) v += __shfl_xor_sync(0xffffffffu, v, off);
    return v;
}

// ------- init (per-launch reset) + att-vector fold (no dependencies) --------
__global__ void k_init(const float* __restrict__ Wg,
                       const float* __restrict__ att_src, const float* __restrict__ att_dst) {
    int b = blockIdx.x, t = threadIdx.x;
    if (b < 196) {
        int i = b * 256 + t;
        int stride = 196 * 256;
        for (int j = i; j < Nn; j += stride) g_deg[j] = 0;
        if (i < 512) { g_sum1[i] = 0.f; g_sumsq1[i] = 0.f; }
        if (i < 256) { g_sum3[i] = 0.f; g_sumsq3[i] = 0.f; }
        if (i < 48)  { g_sum2[i] = 0.f; g_sumsq2[i] = 0.f; }
    } else {
        int hd = b - 196;
        __shared__ float as[64], ad[64];
        if (t < 64) { as[t] = att_src[hd * 64 + t]; ad[t] = att_dst[hd * 64 + t]; }
        __syncthreads();
        if (t < 64) {
            float s = 0.f, d = 0.f;
            #pragma unroll 8
            for (int j = 0; j < 64; j++) {
                float w = Wg[(size_t)(hd * 64 + j) * 64 + t];
                s += as[j] * w;
                d += ad[j] * w;
            }
            g_wsrc[hd * 64 + t] = s;
            g_wdst[hd * 64 + t] = d;
        }
    }
}

// ---- merged: bn1 stats | degree count | batch group boundaries --------------
__global__ void k_pre(const float* __restrict__ x, const int* __restrict__ ei,
                      const int* __restrict__ batch) {
    int b = blockIdx.x;
    if (b < B_STATS) {
        int c = threadIdx.x;  // 512 threads
        float s = 0.f, q = 0.f;
        for (int r = b; r < Nn; r += B_STATS) {
            float v = x[(size_t)r * 544 + c];
            s += v; q += v * v;
        }
        atomicAdd(&g_sum1[c], s);
        atomicAdd(&g_sumsq1[c], q);
    } else if (b < B_STATS + B_DEG) {
        int e = (b - B_STATS) * 512 + threadIdx.x;
        if (e < Ee) atomicAdd(&g_deg[ei[Ee + e]], 1);
    } else {
        int n = (b - B_STATS - B_DEG) * 512 + threadIdx.x;
        if (n < Nn) {
            int bb = batch[n];
            int prev = (n == 0) ? -1 : batch[n - 1];
            for (int g = prev + 1; g <= bb; g++) g_gptr[g] = n;
            if (n == Nn - 1) for (int g = bb + 1; g <= Gg; g++) g_gptr[g] = Nn;
        }
    }
}

// ---- merged: fold bn1 into Wc (blocks 0..15) | scan1: 4x128-chunk sums -----
__global__ void k_fold_scan1(const float* __restrict__ Wc, const float* __restrict__ bc,
                             const float* __restrict__ bn1_g, const float* __restrict__ bn1_b) {
    int b = blockIdx.x, t = threadIdx.x;  // 512 threads
    if (b < 16) {
        __shared__ float red[512];
        const float invN = 1.f / Nn;
        float mean = g_sum1[t] * invN;
        float var  = g_sumsq1[t] * invN - mean * mean;
        float r = rsqrtf(var + EPS);
        float sc = r * bn1_g[t];
        float sh = bn1_b[t] - mean * sc;
        float w = Wc[b * 512 + t];
        g_Wc2[b * 512 + t] = w * sc;
        red[t] = w * sh;
        __syncthreads();
        for (int s = 256; s; s >>= 1) { if (t < s) red[t] += red[t + s]; __syncthreads(); }
        if (t == 0) g_bc2[b] = bc[b] + red[0];
    } else {
        int cquad = b - 16;            // 0..97, covers chunks 4*cquad .. 4*cquad+3
        int idx = cquad * 512 + t;
        int d = (idx < Nn) ? g_deg[idx] : 0;
        int s = warp_sum_i(d);
        __shared__ int sh[16];
        if ((t & 31) == 0) sh[t >> 5] = s;
        __syncthreads();
        if (t < 4) {
            int base = t * 4;
            int a = sh[base] + sh[base + 1] + sh[base + 2] + sh[base + 3];
            g_chunksum[cquad * 4 + t] = a;
        }
    }
}

// ---- merged: scan phase 2+3 (blocks 0..390) | node_z 4/warp (391+) ---------
__global__ void k_scan3_nodez(const float* __restrict__ x,
                              const float* __restrict__ ln_g, const float* __restrict__ ln_b) {
    int b = blockIdx.x, tid = threadIdx.x;  // 128 threads
    if (b < NCH) {
        __shared__ int sh[128];
        __shared__ int ssum[4];
        __shared__ int off_s;
        int v = 0;
        for (int i = tid; i < b; i += 128) v += g_chunksum[i];
        v = warp_sum_i(v);
        if ((tid & 31) == 0) ssum[tid >> 5] = v;
        __syncthreads();
        if (tid == 0) off_s = ssum[0] + ssum[1] + ssum[2] + ssum[3];
        int idx = b * 128 + tid;
        int d = (idx < Nn) ? g_deg[idx] : 0;
        sh[tid] = d;
        __syncthreads();
        for (int off = 1; off < 128; off <<= 1) {
            int u = (tid >= off) ? sh[tid - off] : 0;
            __syncthreads();
            sh[tid] += u;
            __syncthreads();
        }
        if (idx < Nn) {
            int pos = off_s + sh[tid] - d;
            g_rowptr[idx] = pos;
            g_cursor[idx] = pos;
        }
        if (idx == Nn - 1) g_rowptr[Nn] = Ee;
    } else {
        __shared__ float sh_s[48], sh_q[48];
        if (tid < 48) { sh_s[tid] = 0.f; sh_q[tid] = 0.f; }
        __syncthreads();
        int w = tid >> 5, lane = tid & 31;
        int nb = (b - NCH) * 16 + w * 4;   // exact: 3125*16 = 50000

        const float* rows[4];
        float fn[4];
        #pragma unroll
        for (int m = 0; m < 4; m++) {
            rows[m] = x + (size_t)(nb + m) * 544;
            float fv = rows[m][512 + lane];
            float mu = warp_sum(fv) * (1.f / 32.f);
            float qq = warp_sum(fv * fv) * (1.f / 32.f);
            fn[m] = (fv - mu) * rsqrtf(qq - mu * mu + EPS) * ln_g[lane] + ln_b[lane];
        }

        float4 xv[4][4];
        #pragma unroll
        for (int m = 0; m < 4; m++)
            #pragma unroll
            for (int i = 0; i < 4; i++)
                xv[m][i] = *(const float4*)&rows[m][4 * lane + 128 * i];

        int l7 = lane & 7;
        int o_lo = ((l7 & 1) << 2) | (l7 & 2) | ((l7 >> 2) & 1);  // bit-reversed 3 bits
        int grp = lane >> 3;

        #pragma unroll
        for (int p = 0; p < 2; p++) {
            float acc[4][8];
            #pragma unroll
            for (int o = 0; o < 8; o++) {
                int oo = p * 8 + o;
                float a0 = 0.f, a1 = 0.f, a2 = 0.f, a3 = 0.f;
                #pragma unroll
                for (int i = 0; i < 4; i++) {
                    float4 wv = *(const float4*)&g_Wc2[oo * 512 + 4 * lane + 128 * i];
                    a0 += xv[0][i].x * wv.x + xv[0][i].y * wv.y + xv[0][i].z * wv.z + xv[0][i].w * wv.w;
                    a1 += xv[1][i].x * wv.x + xv[1][i].y * wv.y + xv[1][i].z * wv.z + xv[1][i].w * wv.w;
                    a2 += xv[2][i].x * wv.x + xv[2][i].y * wv.y + xv[2][i].z * wv.z + xv[2][i].w * wv.w;
                    a3 += xv[3][i].x * wv.x + xv[3][i].y * wv.y + xv[3][i].z * wv.z + xv[3][i].w * wv.w;
                }
                acc[0][o] = a0; acc[1][o] = a1; acc[2][o] = a2; acc[3][o] = a3;
            }
            // fold 8-vec per node over lanes (3 butterfly steps)
            #pragma unroll
            for (int s = 0; s < 3; s++) {
                const int d = 1 << s;
                const int m2 = 4 >> s;
                bool up = (lane & d) != 0;
                #pragma unroll
                for (int m = 0; m < 4; m++)
                    #pragma unroll
                    for (int j = 0; j < m2; j++) {
                        float mine = up ? acc[m][j + m2] : acc[m][j];
                        float send = up ? acc[m][j] : acc[m][j + m2];
                        acc[m][j] = mine + __shfl_xor_sync(0xffffffffu, send, d);
                    }
            }
            // cross-group sums (complete each node's value on all lanes)
            #pragma unroll
            for (int m = 0; m < 4; m++) {
                acc[m][0] += __shfl_xor_sync(0xffffffffu, acc[m][0], 8);
                acc[m][0] += __shfl_xor_sync(0xffffffffu, acc[m][0], 16);
            }
            float v = grp == 0 ? acc[0][0] : grp == 1 ? acc[1][0] : grp == 2 ? acc[2][0] : acc[3][0];
            int oo = p * 8 + o_lo;
            float xc = v + g_bc2[oo];
            g_z[(size_t)(nb + grp) * 48 + oo] = xc;
            atomicAdd(&sh_s[oo], xc);
            atomicAdd(&sh_q[oo], xc * xc);
        }

        float fsum = 0.f, fq = 0.f;
        #pragma unroll
        for (int m = 0; m < 4; m++) {
            g_z[(size_t)(nb + m) * 48 + 16 + lane] = fn[m];
            fsum += fn[m];
            fq += fn[m] * fn[m];
        }
        atomicAdd(&sh_s[16 + lane], fsum);
        atomicAdd(&sh_q[16 + lane], fq);
        __syncthreads();
        if (tid < 48) { atomicAdd(&g_sum2[tid], sh_s[tid]); atomicAdd(&g_sumsq2[tid], sh_q[tid]); }
    }
}

// ---- merged: fold bn2 into Wp (blocks 0..63) | CSR scatter (blocks 64+) -----
__global__ void k_fold2_scatter(const float* __restrict__ Wp, const float* __restrict__ bp,
                                const float* __restrict__ bn2_g, const float* __restrict__ bn2_b,
                                const int* __restrict__ ei) {
    int b = blockIdx.x, t = threadIdx.x;  // 256 threads
    if (b < 64) {
        __shared__ float red[256];
        float p = 0.f;
        if (t < 48) {
            const float invN = 1.f / Nn;
            float mean = g_sum2[t] * invN;
            float var  = g_sumsq2[t] * invN - mean * mean;
            float r = rsqrtf(var + EPS);
            float sc = r * bn2_g[t];
            float sh = bn2_b[t] - mean * sc;
            float w = Wp[b * 48 + t];
            g_Wp2[b * 48 + t] = w * sc;
            p = w * sh;
        }
        red[t] = p;
        __syncthreads();
        for (int s = 128; s; s >>= 1) { if (t < s) red[t] += red[t + s]; __syncthreads(); }
        if (t == 0) g_bp2[b] = bp[b] + red[0];
    } else {
        int e = (b - 64) * 256 + t;
        int di = ei[Ee + e];
        int pos = atomicAdd(&g_cursor[di], 1);
        g_col[pos] = ei[e];
    }
}

// --------------- per node: t = relu(Wp2 z + bp2), plus attention logits -----
__global__ void k_node_t() {
    __shared__ float wp[64 * 49];
    __shared__ float zb[8][48];
    int tid = threadIdx.x;
    for (int i = tid; i < 64 * 48; i += 256) {
        int o = i / 48, k = i - o * 48;
        wp[o * 49 + k] = g_Wp2[i];
    }
    __syncthreads();
    int w = tid >> 5, lane = tid & 31;
    int n = blockIdx.x * 8 + w;
    const float* zr = g_z + (size_t)n * 48;
    zb[w][lane] = zr[lane];
    if (lane < 16) zb[w][32 + lane] = zr[32 + lane];
    __syncwarp();
    float t0 = g_bp2[lane], t1 = g_bp2[lane + 32];
    #pragma unroll
    for (int k = 0; k < 48; k++) {
        float zv = zb[w][k];
        t0 += wp[lane * 49 + k] * zv;
        t1 += wp[(lane + 32) * 49 + k] * zv;
    }
    t0 = fmaxf(t0, 0.f);
    t1 = fmaxf(t1, 0.f);
    ((float2*)g_t)[(size_t)n * 32 + lane] = make_float2(t0, t1);

    #pragma unroll
    for (int hd = 0; hd < 4; hd++) {
        float ps = t0 * g_wsrc[hd * 64 + lane] + t1 * g_wsrc[hd * 64 + 32 + lane];
        float pd = t0 * g_wdst[hd * 64 + lane] + t1 * g_wdst[hd * 64 + 32 + lane];
        float vs = warp_sum(ps);
        float vd = warp_sum(pd);
        if (lane == 0) { g_asrc[n * 4 + hd] = vs; g_adst[n * 4 + hd] = vd; }
    }
}

// --------- fused softmax + aggregation in t-space: warp per dst node --------
__global__ void k_agg() {
    int tid = threadIdx.x;
    int w = tid >> 5, lane = tid & 31;
    int n = blockIdx.x * 8 + w;
    int r0 = g_rowptr[n], r1 = g_rowptr[n + 1];
    float4 ad = *(const float4*)&g_adst[n * 4];
    const float2* t2 = (const float2*)g_t;

    float acc[8];
    #pragma unroll
    for (int i = 0; i < 8; i++) acc[i] = 0.f;
    float s0 = 0.f, s1 = 0.f, s2 = 0.f, s3 = 0.f;

    for (int base = r0; base < r1; base += 32) {
        int cnt = min(32, r1 - base);
        int si = 0;
        float ex0 = 0.f, ex1 = 0.f, ex2 = 0.f, ex3 = 0.f;
        if (lane < cnt) {
            si = g_col[base + lane];
            float4 as = *(const float4*)&g_asrc[si * 4];
            float e0 = as.x + ad.x, e1 = as.y + ad.y, e2 = as.z + ad.z, e3 = as.w + ad.w;
            e0 = e0 > 0.f ? e0 : 0.2f * e0;
            e1 = e1 > 0.f ? e1 : 0.2f * e1;
            e2 = e2 > 0.f ? e2 : 0.2f * e2;
            e3 = e3 > 0.f ? e3 : 0.2f * e3;
            ex0 = __expf(e0); ex1 = __expf(e1); ex2 = __expf(e2); ex3 = __expf(e3);
            s0 += ex0; s1 += ex1; s2 += ex2; s3 += ex3;
        }
        for (int j = 0; j < cnt; j++) {
            int sj   = __shfl_sync(0xffffffffu, si, j);
            float a0 = __shfl_sync(0xffffffffu, ex0, j);
            float a1 = __shfl_sync(0xffffffffu, ex1, j);
            float a2 = __shfl_sync(0xffffffffu, ex2, j);
            float a3 = __shfl_sync(0xffffffffu, ex3, j);
            float2 u = t2[(size_t)sj * 32 + lane];
            acc[0] += a0 * u.x; acc[1] += a0 * u.y;
            acc[2] += a1 * u.x; acc[3] += a1 * u.y;
            acc[4] += a2 * u.x; acc[5] += a2 * u.y;
            acc[6] += a3 * u.x; acc[7] += a3 * u.y;
        }
    }
    s0 = warp_sum(s0); s1 = warp_sum(s1); s2 = warp_sum(s2); s3 = warp_sum(s3);
    float i0 = 1.f / fmaxf(s0, 1e-16f);
    float i1 = 1.f / fmaxf(s1, 1e-16f);
    float i2 = 1.f / fmaxf(s2, 1e-16f);
    float i3 = 1.f / fmaxf(s3, 1e-16f);
    float* o = g_aggt + (size_t)n * 256;
    o[lane]            = acc[0] * i0;  o[lane + 32]       = acc[1] * i0;
    o[64 + lane]       = acc[2] * i1;  o[64 + 32 + lane]  = acc[3] * i1;
    o[128 + lane]      = acc[4] * i2;  o[128 + 32 + lane] = acc[5] * i2;
    o[192 + lane]      = acc[6] * i3;  o[192 + 32 + lane] = acc[7] * i3;
}

// -------- GEMM: out[:, hd] = aggt[:, hd] @ Wg[hd]^T + reduced bn3 stats ------
// tile 128 nodes x 64 outs, thread 8x4, transposed smem (broadcast-friendly)
__global__ void k_gemm_out(const float* __restrict__ Wg) {
    __shared__ float xs[32 * 132];   // xs[k][n]
    __shared__ float ws[32 * 68];    // ws[k][o]
    __shared__ float rs[64 * 16];
    __shared__ float rq[64 * 16];
    int n0 = blockIdx.x * 128;
    int hd = blockIdx.y, out0 = hd * 64;
    int tid = threadIdx.x;           // 256
    int tx = tid & 15, ty = tid >> 4;

    float acc[8][4];
    #pragma unroll
    for (int i = 0; i < 8; i++)
        #pragma unroll
        for (int o = 0; o < 4; o++) acc[i][o] = 0.f;

    #pragma unroll
    for (int kc = 0; kc < 2; kc++) {
        int kb = kc * 32;
        if (kc) __syncthreads();
        #pragma unroll
        for (int ii = 0; ii < 4; ii++) {
            int i = tid + ii * 256;
            int nr = i >> 3, c4 = (i & 7) << 2;
            float4 v = make_float4(0.f, 0.f, 0.f, 0.f);
            int n = n0 + nr;
            if (n < Nn) v = *(const float4*)&g_aggt[(size_t)n * 256 + out0 + kb + c4];
            xs[(c4 + 0) * 132 + nr] = v.x;
            xs[(c4 + 1) * 132 + nr] = v.y;
            xs[(c4 + 2) * 132 + nr] = v.z;
            xs[(c4 + 3) * 132 + nr] = v.w;
        }
        #pragma unroll
        for (int ii = 0; ii < 2; ii++) {
            int i = tid + ii * 256;
            int orow = i >> 3, c4 = (i & 7) << 2;
            float4 v = *(const float4*)&Wg[(size_t)(out0 + orow) * 64 + kb + c4];
            ws[(c4 + 0) * 68 + orow] = v.x;
            ws[(c4 + 1) * 68 + orow] = v.y;
            ws[(c4 + 2) * 68 + orow] = v.z;
            ws[(c4 + 3) * 68 + orow] = v.w;
        }
        __syncthreads();
        #pragma unroll
        for (int k = 0; k < 32; k++) {
            float4 wv = *(float4*)&ws[k * 68 + tx * 4];
            float4 x0 = *(float4*)&xs[k * 132 + ty * 8];
            float4 x1 = *(float4*)&xs[k * 132 + ty * 8 + 4];
            float xa[8] = {x0.x, x0.y, x0.z, x0.w, x1.x, x1.y, x1.z, x1.w};
            #pragma unroll
            for (int i = 0; i < 8; i++) {
                acc[i][0] += xa[i] * wv.x;
                acc[i][1] += xa[i] * wv.y;
                acc[i][2] += xa[i] * wv.z;
                acc[i][3] += xa[i] * wv.w;
            }
        }
    }
    float ps[4] = {0.f, 0.f, 0.f, 0.f}, pq[4] = {0.f, 0.f, 0.f, 0.f};
    #pragma unroll
    for (int i = 0; i < 8; i++) {
        int n = n0 + ty * 8 + i;
        if (n < Nn) {
            *(float4*)&g_out[(size_t)n * 256 + out0 + tx * 4] =
                make_float4(acc[i][0], acc[i][1], acc[i][2], acc[i][3]);
            #pragma unroll
            for (int o = 0; o < 4; o++) { ps[o] += acc[i][o]; pq[o] += acc[i][o] * acc[i][o]; }
        }
    }
    __syncthreads();
    #pragma unroll
    for (int o = 0; o < 4; o++) {
        rs[(tx * 4 + o) * 16 + ty] = ps[o];
        rq[(tx * 4 + o) * 16 + ty] = pq[o];
    }
    __syncthreads();
    if (tid < 64) {
        float a = 0.f, q = 0.f;
        #pragma unroll
        for (int j = 0; j < 16; j++) { a += rs[tid * 16 + j]; q += rq[tid * 16 + j]; }
        atomicAdd(&g_sum3[out0 + tid], a);
        atomicAdd(&g_sumsq3[out0 + tid], q);
    }
}

// -------- per-group: bn3 + elu + mean-pool (contiguous, no atomics) + head --
__global__ void k_pool_head(const float* __restrict__ bn3_g, const float* __restrict__ bn3_b,
                            const float* __restrict__ W1, const float* __restrict__ b1,
                            const float* __restrict__ W2, const float* __restrict__ b2,
                            float* __restrict__ out) {
    __shared__ float p[256];
    __shared__ float hm[64];
    int g = blockIdx.x, c = threadIdx.x;
    const float invN = 1.f / Nn;
    float mean = g_sum3[c] * invN;
    float var  = g_sumsq3[c] * invN - mean * mean;
    float r = rsqrtf(var + EPS);
    float sc = r * bn3_g[c];
    float sh = bn3_b[c] - mean * sc;
    int r0 = g_gptr[g], r1 = g_gptr[g + 1];
    float s = 0.f;
    for (int n = r0; n < r1; n++) {
        float v = g_out[(size_t)n * 256 + c] * sc + sh;
        v = v > 0.f ? v : (__expf(v) - 1.f);
        s += v;
    }
    p[c] = s / fmaxf((float)(r1 - r0), 1.f);
    __syncthreads();
    if (c < 64) {
        float a = b1[c];
        #pragma unroll 8
        for (int k = 0; k < 256; k++) a += p[k] * W1[c * 256 + k];
        hm[c] = fmaxf(a, 0.f);
    }
    __syncthreads();
    if (c < 2) {
        float a = b2[c];
        #pragma unroll
        for (int k = 0; k < 64; k++) a += hm[k] * W2[c * 64 + k];
        out[g * 2 + c] = a;
    }
}

// ------------------------- launch ---------------------------------------------
extern "C" void kernel_launch(void* const* d_in, const int* in_sizes, int n_in,
                              void* d_out, int out_size) {
    const float* x       = (const float*)d_in[0];
    const int*   ei      = (const int*)d_in[1];
    const int*   batch   = (const int*)d_in[2];
    const float* ln_g    = (const float*)d_in[3];
    const float* ln_b    = (const float*)d_in[4];
    const float* bn1_g   = (const float*)d_in[5];
    const float* bn1_b   = (const float*)d_in[6];
    const float* Wc      = (const float*)d_in[7];
    const float* bc      = (const float*)d_in[8];
    const float* bn2_g   = (const float*)d_in[9];
    const float* bn2_b   = (const float*)d_in[10];
    const float* Wp      = (const float*)d_in[11];
    const float* bp      = (const float*)d_in[12];
    const float* Wg      = (const float*)d_in[13];
    const float* att_src = (const float*)d_in[14];
    const float* att_dst = (const float*)d_in[15];
    // d_in[16] = bg : cancels under bn3 (pure mean shift) -> unused
    const float* bn3_g   = (const float*)d_in[17];
    const float* bn3_b   = (const float*)d_in[18];
    const float* W1      = (const float*)d_in[19];
    const float* b1      = (const float*)d_in[20];
    const float* W2      = (const float*)d_in[21];
    const float* b2      = (const float*)d_in[22];
    float* out = (float*)d_out;

    k_init<<<200, 256>>>(Wg, att_src, att_dst);
    k_pre<<<B_STATS + B_DEG + B_BP, 512>>>(x, ei, batch);
    k_fold_scan1<<<16 + 98, 512>>>(Wc, bc, bn1_g, bn1_b);
    k_scan3_nodez<<<NCH + B_NZ, 128>>>(x, ln_g, ln_b);
    k_fold2_scatter<<<64 + 3125, 256>>>(Wp, bp, bn2_g, bn2_b, ei);
    k_node_t<<<6250, 256>>>();
    k_agg<<<6250, 256>>>();
    dim3 gh(391, 4);
    k_gemm_out<<<gh, 256>>>(Wg);
    k_pool_head<<<Gg, 256>>>(bn3_g, bn3_b, W1, b1, W2, b2, out);
}

// round 11
// speedup vs baseline: 1.2825x; 1.0154x over previous
#include <cuda_runtime.h>
#include <math.h>
#include <stdint.h>

#define Nn 50000
#define Ee 800000
#define Gg 512
#define EPS 1e-5f
#define NCH 391           // chunks of 128 for CSR scan
#define B_STATS 1000
#define B_DEG   1563      // ceil(800000/512)
#define B_BP    98        // ceil(50000/512)
#define B_NZ    3125      // nodez blocks (16 nodes each, 128 thr, 4 warps x 4 nodes)

// ------------------------- device scratch (static, no allocs) ---------------
__device__ float g_sum1[512], g_sumsq1[512];
__device__ __align__(16) float g_Wc2[16 * 512];
__device__ float g_bc2[16];
__device__ __align__(16) float g_z[(size_t)Nn * 48];
__device__ float g_sum2[48], g_sumsq2[48];
__device__ float g_Wp2[64 * 48], g_bp2[64];
__device__ __align__(16) float g_t[(size_t)Nn * 64];   // interleaved (k, k+32) float2
__device__ float g_wsrc[4 * 64], g_wdst[4 * 64];
__device__ __align__(16) float g_asrc[Nn * 4];
__device__ __align__(16) float g_adst[Nn * 4];
__device__ int g_deg[Nn];
__device__ int g_rowptr[Nn + 1];
__device__ int g_cursor[Nn];
__device__ int g_chunksum[392];
__device__ int g_col[Ee];
__device__ int g_gptr[Gg + 1];
__device__ __align__(16) float g_aggt[(size_t)Nn * 256];
__device__ __align__(16) float g_out[(size_t)Nn * 256];
__device__ float g_sum3[256], g_sumsq3[256];

// ------------------------- helpers ------------------------------------------
__device__ __forceinline__ float warp_sum(float v) {
    #pragma unroll
    for (int off = 16; off; off >>= 1) v += __shfl_xor_sync(0xffffffffu, v, off);
    return v;
}
__device__ __forceinline__ int warp_sum_i(int v) {
    #pragma unroll
    for (int off = 16; off; off >>= 1) v += __shfl_xor_sync(0xffffffffu, v, off);
    return v;
}

// ---- packed f32x2 (sm_103a): 2x fp32 FMA throughput, exact fp32 rounding ----
__device__ __forceinline__ unsigned long long f2pk(float lo, float hi) {
    unsigned long long r;
    asm("mov.b64 %0, {%1, %2};" : "=l"(r) : "f"(lo), "f"(hi));
    return r;
}
__device__ __forceinline__ unsigned long long ffma2(unsigned long long a,
                                                    unsigned long long b,
                                                    unsigned long long c) {
    unsigned long long d;
    asm("fma.rn.f32x2 %0, %1, %2, %3;" : "=l"(d) : "l"(a), "l"(b), "l"(c));
    return d;
}
__device__ __forceinline__ void f2upk(unsigned long long v, float& lo, float& hi) {
    asm("mov.b64 {%0, %1}, %2;" : "=f"(lo), "=f"(hi) : "l"(v));
}

// ------- init (per-launch reset) + att-vector fold (no dependencies) --------
__global__ void k_init(const float* __restrict__ Wg,
                       const float* __restrict__ att_src, const float* __restrict__ att_dst) {
    int b = blockIdx.x, t = threadIdx.x;
    if (b < 196) {
        int i = b * 256 + t;
        int stride = 196 * 256;
        for (int j = i; j < Nn; j += stride) g_deg[j] = 0;
        if (i < 512) { g_sum1[i] = 0.f; g_sumsq1[i] = 0.f; }
        if (i < 256) { g_sum3[i] = 0.f; g_sumsq3[i] = 0.f; }
        if (i < 48)  { g_sum2[i] = 0.f; g_sumsq2[i] = 0.f; }
    } else {
        int hd = b - 196;
        __shared__ float as[64], ad[64];
        if (t < 64) { as[t] = att_src[hd * 64 + t]; ad[t] = att_dst[hd * 64 + t]; }
        __syncthreads();
        if (t < 64) {
            float s = 0.f, d = 0.f;
            #pragma unroll 8
            for (int j = 0; j < 64; j++) {
                float w = Wg[(size_t)(hd * 64 + j) * 64 + t];
                s += as[j] * w;
                d += ad[j] * w;
            }
            g_wsrc[hd * 64 + t] = s;
            g_wdst[hd * 64 + t] = d;
        }
    }
}

// ---- merged: bn1 stats | degree count | batch group boundaries --------------
__global__ void k_pre(const float* __restrict__ x, const int* __restrict__ ei,
                      const int* __restrict__ batch) {
    int b = blockIdx.x;
    if (b < B_STATS) {
        int c = threadIdx.x;  // 512 threads
        float s = 0.f, q = 0.f;
        for (int r = b; r < Nn; r += B_STATS) {
            float v = x[(size_t)r * 544 + c];
            s += v; q += v * v;
        }
        atomicAdd(&g_sum1[c], s);
        atomicAdd(&g_sumsq1[c], q);
    } else if (b < B_STATS + B_DEG) {
        int e = (b - B_STATS) * 512 + threadIdx.x;
        if (e < Ee) atomicAdd(&g_deg[ei[Ee + e]], 1);
    } else {
        int n = (b - B_STATS - B_DEG) * 512 + threadIdx.x;
        if (n < Nn) {
            int bb = batch[n];
            int prev = (n == 0) ? -1 : batch[n - 1];
            for (int g = prev + 1; g <= bb; g++) g_gptr[g] = n;
            if (n == Nn - 1) for (int g = bb + 1; g <= Gg; g++) g_gptr[g] = Nn;
        }
    }
}

// ---- merged: fold bn1 into Wc (blocks 0..15) | scan1: 4x128-chunk sums -----
__global__ void k_fold_scan1(const float* __restrict__ Wc, const float* __restrict__ bc,
                             const float* __restrict__ bn1_g, const float* __restrict__ bn1_b) {
    int b = blockIdx.x, t = threadIdx.x;  // 512 threads
    if (b < 16) {
        __shared__ float red[512];
        const float invN = 1.f / Nn;
        float mean = g_sum1[t] * invN;
        float var  = g_sumsq1[t] * invN - mean * mean;
        float r = rsqrtf(var + EPS);
        float sc = r * bn1_g[t];
        float sh = bn1_b[t] - mean * sc;
        float w = Wc[b * 512 + t];
        g_Wc2[b * 512 + t] = w * sc;
        red[t] = w * sh;
        __syncthreads();
        for (int s = 256; s; s >>= 1) { if (t < s) red[t] += red[t + s]; __syncthreads(); }
        if (t == 0) g_bc2[b] = bc[b] + red[0];
    } else {
        int cquad = b - 16;            // 0..97, covers chunks 4*cquad .. 4*cquad+3
        int idx = cquad * 512 + t;
        int d = (idx < Nn) ? g_deg[idx] : 0;
        int s = warp_sum_i(d);
        __shared__ int sh[16];
        if ((t & 31) == 0) sh[t >> 5] = s;
        __syncthreads();
        if (t < 4) {
            int base = t * 4;
            int a = sh[base] + sh[base + 1] + sh[base + 2] + sh[base + 3];
            g_chunksum[cquad * 4 + t] = a;
        }
    }
}

// ---- merged: scan phase 2+3 (blocks 0..390) | node_z 4/warp (391+) ---------
__global__ void k_scan3_nodez(const float* __restrict__ x,
                              const float* __restrict__ ln_g, const float* __restrict__ ln_b) {
    int b = blockIdx.x, tid = threadIdx.x;  // 128 threads
    if (b < NCH) {
        __shared__ int sh[128];
        __shared__ int ssum[4];
        __shared__ int off_s;
        int v = 0;
        for (int i = tid; i < b; i += 128) v += g_chunksum[i];
        v = warp_sum_i(v);
        if ((tid & 31) == 0) ssum[tid >> 5] = v;
        __syncthreads();
        if (tid == 0) off_s = ssum[0] + ssum[1] + ssum[2] + ssum[3];
        int idx = b * 128 + tid;
        int d = (idx < Nn) ? g_deg[idx] : 0;
        sh[tid] = d;
        __syncthreads();
        for (int off = 1; off < 128; off <<= 1) {
            int u = (tid >= off) ? sh[tid - off] : 0;
            __syncthreads();
            sh[tid] += u;
            __syncthreads();
        }
        if (idx < Nn) {
            int pos = off_s + sh[tid] - d;
            g_rowptr[idx] = pos;
            g_cursor[idx] = pos;
        }
        if (idx == Nn - 1) g_rowptr[Nn] = Ee;
    } else {
        __shared__ float sh_s[48], sh_q[48];
        if (tid < 48) { sh_s[tid] = 0.f; sh_q[tid] = 0.f; }
        __syncthreads();
        int w = tid >> 5, lane = tid & 31;
        int nb = (b - NCH) * 16 + w * 4;   // exact: 3125*16 = 50000

        const float* rows[4];
        float fn[4];
        #pragma unroll
        for (int m = 0; m < 4; m++) {
            rows[m] = x + (size_t)(nb + m) * 544;
            float fv = rows[m][512 + lane];
            float mu = warp_sum(fv) * (1.f / 32.f);
            float qq = warp_sum(fv * fv) * (1.f / 32.f);
            fn[m] = (fv - mu) * rsqrtf(qq - mu * mu + EPS) * ln_g[lane] + ln_b[lane];
        }

        // load x rows packed: 8 u64 pairs per node (16 floats per lane)
        unsigned long long xp[4][8];
        #pragma unroll
        for (int m = 0; m < 4; m++)
            #pragma unroll
            for (int i = 0; i < 4; i++) {
                ulonglong2 xq = *(const ulonglong2*)&rows[m][4 * lane + 128 * i];
                xp[m][i * 2]     = xq.x;
                xp[m][i * 2 + 1] = xq.y;
            }

        int l7 = lane & 7;
        int o_lo = ((l7 & 1) << 2) | (l7 & 2) | ((l7 >> 2) & 1);  // bit-reversed 3 bits
        int grp = lane >> 3;

        #pragma unroll
        for (int p = 0; p < 2; p++) {
            float acc[4][8];
            #pragma unroll
            for (int o = 0; o < 8; o++) {
                int oo = p * 8 + o;
                unsigned long long ap0 = 0ull, ap1 = 0ull, ap2 = 0ull, ap3 = 0ull;
                #pragma unroll
                for (int i = 0; i < 4; i++) {
                    ulonglong2 wq = *(const ulonglong2*)&g_Wc2[oo * 512 + 4 * lane + 128 * i];
                    ap0 = ffma2(xp[0][i * 2], wq.x, ap0);
                    ap0 = ffma2(xp[0][i * 2 + 1], wq.y, ap0);
                    ap1 = ffma2(xp[1][i * 2], wq.x, ap1);
                    ap1 = ffma2(xp[1][i * 2 + 1], wq.y, ap1);
                    ap2 = ffma2(xp[2][i * 2], wq.x, ap2);
                    ap2 = ffma2(xp[2][i * 2 + 1], wq.y, ap2);
                    ap3 = ffma2(xp[3][i * 2], wq.x, ap3);
                    ap3 = ffma2(xp[3][i * 2 + 1], wq.y, ap3);
                }
                float lo, hi;
                f2upk(ap0, lo, hi); acc[0][o] = lo + hi;
                f2upk(ap1, lo, hi); acc[1][o] = lo + hi;
                f2upk(ap2, lo, hi); acc[2][o] = lo + hi;
                f2upk(ap3, lo, hi); acc[3][o] = lo + hi;
            }
            // fold 8-vec per node over lanes (3 butterfly steps)
            #pragma unroll
            for (int s = 0; s < 3; s++) {
                const int d = 1 << s;
                const int m2 = 4 >> s;
                bool up = (lane & d) != 0;
                #pragma unroll
                for (int m = 0; m < 4; m++)
                    #pragma unroll
                    for (int j = 0; j < m2; j++) {
                        float mine = up ? acc[m][j + m2] : acc[m][j];
                        float send = up ? acc[m][j] : acc[m][j + m2];
                        acc[m][j] = mine + __shfl_xor_sync(0xffffffffu, send, d);
                    }
            }
            // cross-group sums (complete each node's value on all lanes)
            #pragma unroll
            for (int m = 0; m < 4; m++) {
                acc[m][0] += __shfl_xor_sync(0xffffffffu, acc[m][0], 8);
                acc[m][0] += __shfl_xor_sync(0xffffffffu, acc[m][0], 16);
            }
            float v = grp == 0 ? acc[0][0] : grp == 1 ? acc[1][0] : grp == 2 ? acc[2][0] : acc[3][0];
            int oo = p * 8 + o_lo;
            float xc = v + g_bc2[oo];
            g_z[(size_t)(nb + grp) * 48 + oo] = xc;
            atomicAdd(&sh_s[oo], xc);
            atomicAdd(&sh_q[oo], xc * xc);
        }

        float fsum = 0.f, fq = 0.f;
        #pragma unroll
        for (int m = 0; m < 4; m++) {
            g_z[(size_t)(nb + m) * 48 + 16 + lane] = fn[m];
            fsum += fn[m];
            fq += fn[m] * fn[m];
        }
        atomicAdd(&sh_s[16 + lane], fsum);
        atomicAdd(&sh_q[16 + lane], fq);
        __syncthreads();
        if (tid < 48) { atomicAdd(&g_sum2[tid], sh_s[tid]); atomicAdd(&g_sumsq2[tid], sh_q[tid]); }
    }
}

// ---- merged: fold bn2 into Wp (blocks 0..63) | CSR scatter (blocks 64+) -----
__global__ void k_fold2_scatter(const float* __restrict__ Wp, const float* __restrict__ bp,
                                const float* __restrict__ bn2_g, const float* __restrict__ bn2_b,
                                const int* __restrict__ ei) {
    int b = blockIdx.x, t = threadIdx.x;  // 256 threads
    if (b < 64) {
        __shared__ float red[256];
        float p = 0.f;
        if (t < 48) {
            const float invN = 1.f / Nn;
            float mean = g_sum2[t] * invN;
            float var  = g_sumsq2[t] * invN - mean * mean;
            float r = rsqrtf(var + EPS);
            float sc = r * bn2_g[t];
            float sh = bn2_b[t] - mean * sc;
            float w = Wp[b * 48 + t];
            g_Wp2[b * 48 + t] = w * sc;
            p = w * sh;
        }
        red[t] = p;
        __syncthreads();
        for (int s = 128; s; s >>= 1) { if (t < s) red[t] += red[t + s]; __syncthreads(); }
        if (t == 0) g_bp2[b] = bp[b] + red[0];
    } else {
        int e = (b - 64) * 256 + t;
        int di = ei[Ee + e];
        int pos = atomicAdd(&g_cursor[di], 1);
        g_col[pos] = ei[e];
    }
}

// --------------- per node: t = relu(Wp2 z + bp2), plus attention logits -----
__global__ void k_node_t() {
    __shared__ float wp[64 * 49];
    __shared__ float zb[8][48];
    int tid = threadIdx.x;
    for (int i = tid; i < 64 * 48; i += 256) {
        int o = i / 48, k = i - o * 48;
        wp[o * 49 + k] = g_Wp2[i];
    }
    __syncthreads();
    int w = tid >> 5, lane = tid & 31;
    int n = blockIdx.x * 8 + w;
    const float* zr = g_z + (size_t)n * 48;
    zb[w][lane] = zr[lane];
    if (lane < 16) zb[w][32 + lane] = zr[32 + lane];
    __syncwarp();
    float t0 = g_bp2[lane], t1 = g_bp2[lane + 32];
    #pragma unroll
    for (int k = 0; k < 48; k++) {
        float zv = zb[w][k];
        t0 += wp[lane * 49 + k] * zv;
        t1 += wp[(lane + 32) * 49 + k] * zv;
    }
    t0 = fmaxf(t0, 0.f);
    t1 = fmaxf(t1, 0.f);
    ((float2*)g_t)[(size_t)n * 32 + lane] = make_float2(t0, t1);

    #pragma unroll
    for (int hd = 0; hd < 4; hd++) {
        float ps = t0 * g_wsrc[hd * 64 + lane] + t1 * g_wsrc[hd * 64 + 32 + lane];
        float pd = t0 * g_wdst[hd * 64 + lane] + t1 * g_wdst[hd * 64 + 32 + lane];
        float vs = warp_sum(ps);
        float vd = warp_sum(pd);
        if (lane == 0) { g_asrc[n * 4 + hd] = vs; g_adst[n * 4 + hd] = vd; }
    }
}

// --------- fused softmax + aggregation in t-space: warp per dst node --------
__global__ void k_agg() {
    int tid = threadIdx.x;
    int w = tid >> 5, lane = tid & 31;
    int n = blockIdx.x * 8 + w;
    int r0 = g_rowptr[n], r1 = g_rowptr[n + 1];
    float4 ad = *(const float4*)&g_adst[n * 4];
    const unsigned long long* t2u = (const unsigned long long*)g_t;

    unsigned long long acc2[4] = {0ull, 0ull, 0ull, 0ull};
    float s0 = 0.f, s1 = 0.f, s2 = 0.f, s3 = 0.f;

    for (int base = r0; base < r1; base += 32) {
        int cnt = min(32, r1 - base);
        int si = 0;
        float ex0 = 0.f, ex1 = 0.f, ex2 = 0.f, ex3 = 0.f;
        if (lane < cnt) {
            si = g_col[base + lane];
            float4 as = *(const float4*)&g_asrc[si * 4];
            float e0 = as.x + ad.x, e1 = as.y + ad.y, e2 = as.z + ad.z, e3 = as.w + ad.w;
            e0 = e0 > 0.f ? e0 : 0.2f * e0;
            e1 = e1 > 0.f ? e1 : 0.2f * e1;
            e2 = e2 > 0.f ? e2 : 0.2f * e2;
            e3 = e3 > 0.f ? e3 : 0.2f * e3;
            ex0 = __expf(e0); ex1 = __expf(e1); ex2 = __expf(e2); ex3 = __expf(e3);
            s0 += ex0; s1 += ex1; s2 += ex2; s3 += ex3;
        }
        for (int j = 0; j < cnt; j++) {
            int sj   = __shfl_sync(0xffffffffu, si, j);
            float a0 = __shfl_sync(0xffffffffu, ex0, j);
            float a1 = __shfl_sync(0xffffffffu, ex1, j);
            float a2 = __shfl_sync(0xffffffffu, ex2, j);
            float a3 = __shfl_sync(0xffffffffu, ex3, j);
            unsigned long long u = t2u[(size_t)sj * 32 + lane];
            acc2[0] = ffma2(f2pk(a0, a0), u, acc2[0]);
            acc2[1] = ffma2(f2pk(a1, a1), u, acc2[1]);
            acc2[2] = ffma2(f2pk(a2, a2), u, acc2[2]);
            acc2[3] = ffma2(f2pk(a3, a3), u, acc2[3]);
        }
    }
    float acc[8];
    f2upk(acc2[0], acc[0], acc[1]);
    f2upk(acc2[1], acc[2], acc[3]);
    f2upk(acc2[2], acc[4], acc[5]);
    f2upk(acc2[3], acc[6], acc[7]);
    s0 = warp_sum(s0); s1 = warp_sum(s1); s2 = warp_sum(s2); s3 = warp_sum(s3);
    float i0 = 1.f / fmaxf(s0, 1e-16f);
    float i1 = 1.f / fmaxf(s1, 1e-16f);
    float i2 = 1.f / fmaxf(s2, 1e-16f);
    float i3 = 1.f / fmaxf(s3, 1e-16f);
    float* o = g_aggt + (size_t)n * 256;
    o[lane]            = acc[0] * i0;  o[lane + 32]       = acc[1] * i0;
    o[64 + lane]       = acc[2] * i1;  o[64 + 32 + lane]  = acc[3] * i1;
    o[128 + lane]      = acc[4] * i2;  o[128 + 32 + lane] = acc[5] * i2;
    o[192 + lane]      = acc[6] * i3;  o[192 + 32 + lane] = acc[7] * i3;
}

// -------- GEMM: out[:, hd] = aggt[:, hd] @ Wg[hd]^T + reduced bn3 stats ------
// tile 128 nodes x 64 outs, thread 8x4, transposed smem, f32x2 inner
__global__ void k_gemm_out(const float* __restrict__ Wg) {
    __shared__ float xs[32 * 132];   // xs[k][n]
    __shared__ float ws[32 * 68];    // ws[k][o]
    __shared__ float rs[64 * 16];
    __shared__ float rq[64 * 16];
    int n0 = blockIdx.x * 128;
    int hd = blockIdx.y, out0 = hd * 64;
    int tid = threadIdx.x;           // 256
    int tx = tid & 15, ty = tid >> 4;

    unsigned long long acc2[8][2];
    #pragma unroll
    for (int i = 0; i < 8; i++) { acc2[i][0] = 0ull; acc2[i][1] = 0ull; }

    #pragma unroll
    for (int kc = 0; kc < 2; kc++) {
        int kb = kc * 32;
        if (kc) __syncthreads();
        #pragma unroll
        for (int ii = 0; ii < 4; ii++) {
            int i = tid + ii * 256;
            int nr = i >> 3, c4 = (i & 7) << 2;
            float4 v = make_float4(0.f, 0.f, 0.f, 0.f);
            int n = n0 + nr;
            if (n < Nn) v = *(const float4*)&g_aggt[(size_t)n * 256 + out0 + kb + c4];
            xs[(c4 + 0) * 132 + nr] = v.x;
            xs[(c4 + 1) * 132 + nr] = v.y;
            xs[(c4 + 2) * 132 + nr] = v.z;
            xs[(c4 + 3) * 132 + nr] = v.w;
        }
        #pragma unroll
        for (int ii = 0; ii < 2; ii++) {
            int i = tid + ii * 256;
            int orow = i >> 3, c4 = (i & 7) << 2;
            float4 v = *(const float4*)&Wg[(size_t)(out0 + orow) * 64 + kb + c4];
            ws[(c4 + 0) * 68 + orow] = v.x;
            ws[(c4 + 1) * 68 + orow] = v.y;
            ws[(c4 + 2) * 68 + orow] = v.z;
            ws[(c4 + 3) * 68 + orow] = v.w;
        }
        __syncthreads();
        #pragma unroll
        for (int k = 0; k < 32; k++) {
            float4 wv = *(float4*)&ws[k * 68 + tx * 4];
            unsigned long long wp0 = f2pk(wv.x, wv.y);
            unsigned long long wp1 = f2pk(wv.z, wv.w);
            float4 x0 = *(float4*)&xs[k * 132 + ty * 8];
            float4 x1 = *(float4*)&xs[k * 132 + ty * 8 + 4];
            float xa[8] = {x0.x, x0.y, x0.z, x0.w, x1.x, x1.y, x1.z, x1.w};
            #pragma unroll
            for (int i = 0; i < 8; i++) {
                unsigned long long xd = f2pk(xa[i], xa[i]);
                acc2[i][0] = ffma2(xd, wp0, acc2[i][0]);
                acc2[i][1] = ffma2(xd, wp1, acc2[i][1]);
            }
        }
    }
    float ps[4] = {0.f, 0.f, 0.f, 0.f}, pq[4] = {0.f, 0.f, 0.f, 0.f};
    #pragma unroll
    for (int i = 0; i < 8; i++) {
        int n = n0 + ty * 8 + i;
        if (n < Nn) {
            float a0, a1, a2, a3;
            f2upk(acc2[i][0], a0, a1);
            f2upk(acc2[i][1], a2, a3);
            *(float4*)&g_out[(size_t)n * 256 + out0 + tx * 4] = make_float4(a0, a1, a2, a3);
            ps[0] += a0; pq[0] += a0 * a0;
            ps[1] += a1; pq[1] += a1 * a1;
            ps[2] += a2; pq[2] += a2 * a2;
            ps[3] += a3; pq[3] += a3 * a3;
        }
    }
    __syncthreads();
    #pragma unroll
    for (int o = 0; o < 4; o++) {
        rs[(tx * 4 + o) * 16 + ty] = ps[o];
        rq[(tx * 4 + o) * 16 + ty] = pq[o];
    }
    __syncthreads();
    if (tid < 64) {
        float a = 0.f, q = 0.f;
        #pragma unroll
        for (int j = 0; j < 16; j++) { a += rs[tid * 16 + j]; q += rq[tid * 16 + j]; }
        atomicAdd(&g_sum3[out0 + tid], a);
        atomicAdd(&g_sumsq3[out0 + tid], q);
    }
}

// -------- per-group: bn3 + elu + mean-pool (contiguous, no atomics) + head --
__global__ void k_pool_head(const float* __restrict__ bn3_g, const float* __restrict__ bn3_b,
                            const float* __restrict__ W1, const float* __restrict__ b1,
                            const float* __restrict__ W2, const float* __restrict__ b2,
                            float* __restrict__ out) {
    __shared__ float p[256];
    __shared__ float hm[64];
    int g = blockIdx.x, c = threadIdx.x;
    const float invN = 1.f / Nn;
    float mean = g_sum3[c] * invN;
    float var  = g_sumsq3[c] * invN - mean * mean;
    float r = rsqrtf(var + EPS);
    float sc = r * bn3_g[c];
    float sh = bn3_b[c] - mean * sc;
    int r0 = g_gptr[g], r1 = g_gptr[g + 1];
    float s = 0.f;
    for (int n = r0; n < r1; n++) {
        float v = g_out[(size_t)n * 256 + c] * sc + sh;
        v = v > 0.f ? v : (__expf(v) - 1.f);
        s += v;
    }
    p[c] = s / fmaxf((float)(r1 - r0), 1.f);
    __syncthreads();
    if (c < 64) {
        float a = b1[c];
        #pragma unroll 8
        for (int k = 0; k < 256; k++) a += p[k] * W1[c * 256 + k];
        hm[c] = fmaxf(a, 0.f);
    }
    __syncthreads();
    if (c < 2) {
        float a = b2[c];
        #pragma unroll
        for (int k = 0; k < 64; k++) a += hm[k] * W2[c * 64 + k];
        out[g * 2 + c] = a;
    }
}

// ------------------------- launch ---------------------------------------------
extern "C" void kernel_launch(void* const* d_in, const int* in_sizes, int n_in,
                              void* d_out, int out_size) {
    const float* x       = (const float*)d_in[0];
    const int*   ei      = (const int*)d_in[1];
    const int*   batch   = (const int*)d_in[2];
    const float* ln_g    = (const float*)d_in[3];
    const float* ln_b    = (const float*)d_in[4];
    const float* bn1_g   = (const float*)d_in[5];
    const float* bn1_b   = (const float*)d_in[6];
    const float* Wc      = (const float*)d_in[7];
    const float* bc      = (const float*)d_in[8];
    const float* bn2_g   = (const float*)d_in[9];
    const float* bn2_b   = (const float*)d_in[10];
    const float* Wp      = (const float*)d_in[11];
    const float* bp      = (const float*)d_in[12];
    const float* Wg      = (const float*)d_in[13];
    const float* att_src = (const float*)d_in[14];
    const float* att_dst = (const float*)d_in[15];
    // d_in[16] = bg : cancels under bn3 (pure mean shift) -> unused
    const float* bn3_g   = (const float*)d_in[17];
    const float* bn3_b   = (const float*)d_in[18];
    const float* W1      = (const float*)d_in[19];
    const float* b1      = (const float*)d_in[20];
    const float* W2      = (const float*)d_in[21];
    const float* b2      = (const float*)d_in[22];
    float* out = (float*)d_out;

    k_init<<<200, 256>>>(Wg, att_src, att_dst);
    k_pre<<<B_STATS + B_DEG + B_BP, 512>>>(x, ei, batch);
    k_fold_scan1<<<16 + 98, 512>>>(Wc, bc, bn1_g, bn1_b);
    k_scan3_nodez<<<NCH + B_NZ, 128>>>(x, ln_g, ln_b);
    k_fold2_scatter<<<64 + 3125, 256>>>(Wp, bp, bn2_g, bn2_b, ei);
    k_node_t<<<6250, 256>>>();
    k_agg<<<6250, 256>>>();
    dim3 gh(391, 4);
    k_gemm_out<<<gh, 256>>>(Wg);
    k_pool_head<<<Gg, 256>>>(bn3_g, bn3_b, W1, b1, W2, b2, out);
}